// round 1
// baseline (speedup 1.0000x reference)
#include <cuda_runtime.h>
#include <math.h>

#define B_   8
#define S_   1024
#define H_   12
#define D_   64
#define HID  768
#define KTOP 6
#define NROWS (B_ * S_)        // 8192
#define NZ    (B_ * H_)        // 96

// ---------------- scratch (device globals; no allocation allowed) ----------------
__device__ float g_rpart[B_ * 32 * HID];           // partial column sums for router mean
__device__ float g_mask[NZ];                       // 0/1 per (b,h)
__device__ float g_q[NZ * S_ * D_];
__device__ float g_k[NZ * S_ * D_];
__device__ float g_v[NZ * S_ * D_];
__device__ float g_scores[100663296];              // 96 * 1024 * 1024 (probs in-place)
__device__ float g_ctx[NZ * S_ * D_];
__device__ float g_x[NROWS * HID];                 // pre-LN activations

// ---------------- stage 1: partial column sums over S for router mean ----------------
__global__ void mean_partial_kernel(const float* __restrict__ X) {
    int b = blockIdx.x;       // 0..7
    int chunk = blockIdx.y;   // 0..31 (32 rows each)
    int tid = threadIdx.x;    // 256
    const float* Xb = X + ((size_t)b * S_ + chunk * 32) * HID;
    #pragma unroll
    for (int j = 0; j < 3; j++) {
        int c = tid + j * 256;
        float s = 0.f;
        #pragma unroll 8
        for (int r = 0; r < 32; r++) s += Xb[r * HID + c];
        g_rpart[(b * 32 + chunk) * HID + c] = s;
    }
}

// ---------------- stage 2: router logits + top-6 mask ----------------
__global__ void router_kernel(const float* __restrict__ Wr, const float* __restrict__ br) {
    __shared__ float rin[HID];
    __shared__ float logits[H_];
    int b = blockIdx.x;
    int tid = threadIdx.x;
    #pragma unroll
    for (int j = 0; j < 3; j++) {
        int c = tid + j * 256;
        float s = 0.f;
        #pragma unroll
        for (int p = 0; p < 32; p++) s += g_rpart[(b * 32 + p) * HID + c];
        rin[c] = s * (1.0f / S_);
    }
    __syncthreads();
    int warp = tid >> 5, lane = tid & 31;
    for (int h = warp; h < H_; h += 8) {
        float s = 0.f;
        for (int c = lane; c < HID; c += 32) s += rin[c] * Wr[c * H_ + h];
        #pragma unroll
        for (int o = 16; o > 0; o >>= 1) s += __shfl_xor_sync(0xffffffffu, s, o);
        if (lane == 0) logits[h] = s + br[h];
    }
    __syncthreads();
    if (tid < H_) {
        float v = logits[tid];
        int rank = 0;
        #pragma unroll
        for (int j = 0; j < H_; j++) {
            float u = logits[j];
            if (u > v || (u == v && j < tid)) rank++;
        }
        g_mask[b * H_ + tid] = (rank < KTOP) ? 1.0f : 0.0f;
    }
}

// ---------------- tile-MAC shared by all GEMMs ----------------
#define TILE_MAC(AS, BS, TY4, TX4, ACC)                                     \
    _Pragma("unroll")                                                        \
    for (int kk = 0; kk < 16; kk++) {                                        \
        float4 a4 = *(float4*)&AS[kk][TY4];                                  \
        float4 b4 = *(float4*)&BS[kk][TX4];                                  \
        float ar[4] = {a4.x, a4.y, a4.z, a4.w};                              \
        float brr[4] = {b4.x, b4.y, b4.z, b4.w};                             \
        _Pragma("unroll")                                                    \
        for (int i = 0; i < 4; i++)                                          \
            _Pragma("unroll")                                                \
            for (int j = 0; j < 4; j++)                                      \
                ACC[i][j] = fmaf(ar[i], brr[j], ACC[i][j]);                  \
    }

// ---------------- QKV projection: X(8192x768) @ W(768x768), mask + scatter epilogue ----------------
__global__ void __launch_bounds__(256) qkv_gemm(
    const float* __restrict__ X,
    const float* __restrict__ Wq, const float* __restrict__ bq,
    const float* __restrict__ Wk, const float* __restrict__ bk,
    const float* __restrict__ Wv, const float* __restrict__ bv) {
    const float* W; const float* bias; float* out;
    int z = blockIdx.z;
    if (z == 0)      { W = Wq; bias = bq; out = g_q; }
    else if (z == 1) { W = Wk; bias = bk; out = g_k; }
    else             { W = Wv; bias = bv; out = g_v; }

    __shared__ float As[16][64];
    __shared__ float Bs[16][64];
    int tid = threadIdx.x;
    int tx4 = (tid & 15) << 2, ty4 = (tid >> 4) << 2;
    int m0 = blockIdx.y * 64;
    int n0 = blockIdx.x * 64;
    float acc[4][4] = {};

    int ra = tid >> 2, ca = (tid & 3) << 2;
    int rb = tid >> 4, cb = (tid & 15) << 2;
    for (int k0 = 0; k0 < HID; k0 += 16) {
        float4 av = *(const float4*)&X[(size_t)(m0 + ra) * HID + k0 + ca];
        As[ca + 0][ra] = av.x; As[ca + 1][ra] = av.y;
        As[ca + 2][ra] = av.z; As[ca + 3][ra] = av.w;
        *(float4*)&Bs[rb][cb] = *(const float4*)&W[(size_t)(k0 + rb) * HID + n0 + cb];
        __syncthreads();
        TILE_MAC(As, Bs, ty4, tx4, acc)
        __syncthreads();
    }
    int h = n0 >> 6;
    int bb = m0 >> 10;
    int s0 = m0 & (S_ - 1);
    float mk = g_mask[bb * H_ + h];
    #pragma unroll
    for (int i = 0; i < 4; i++) {
        int s = s0 + ty4 + i;
        float* orow = out + (((size_t)(bb * H_ + h) * S_ + s) << 6);
        float4 bv4 = *(const float4*)&bias[n0 + tx4];
        float4 o;
        o.x = (acc[i][0] + bv4.x) * mk;
        o.y = (acc[i][1] + bv4.y) * mk;
        o.z = (acc[i][2] + bv4.z) * mk;
        o.w = (acc[i][3] + bv4.w) * mk;
        *(float4*)&orow[tx4] = o;
    }
}

// ---------------- scores = Q Kt / 8 per active (b,h): NT gemm M=N=1024 K=64 ----------------
__global__ void __launch_bounds__(256) score_gemm() {
    int z = blockIdx.z;
    if (g_mask[z] == 0.f) return;
    const float* A  = g_q + (size_t)z * S_ * D_;
    const float* Bk = g_k + (size_t)z * S_ * D_;
    float* C = g_scores + (size_t)z * S_ * S_;

    __shared__ float As[16][64];
    __shared__ float Bs[16][64];
    int tid = threadIdx.x;
    int tx4 = (tid & 15) << 2, ty4 = (tid >> 4) << 2;
    int m0 = blockIdx.y * 64;
    int n0 = blockIdx.x * 64;
    float acc[4][4] = {};
    int ra = tid >> 2, ca = (tid & 3) << 2;
    for (int k0 = 0; k0 < D_; k0 += 16) {
        float4 av = *(const float4*)&A[(size_t)(m0 + ra) * D_ + k0 + ca];
        As[ca + 0][ra] = av.x; As[ca + 1][ra] = av.y;
        As[ca + 2][ra] = av.z; As[ca + 3][ra] = av.w;
        float4 bv = *(const float4*)&Bk[(size_t)(n0 + ra) * D_ + k0 + ca];
        Bs[ca + 0][ra] = bv.x; Bs[ca + 1][ra] = bv.y;
        Bs[ca + 2][ra] = bv.z; Bs[ca + 3][ra] = bv.w;
        __syncthreads();
        TILE_MAC(As, Bs, ty4, tx4, acc)
        __syncthreads();
    }
    #pragma unroll
    for (int i = 0; i < 4; i++) {
        float* crow = C + (size_t)(m0 + ty4 + i) * S_ + n0;
        float4 o;
        o.x = acc[i][0] * 0.125f; o.y = acc[i][1] * 0.125f;
        o.z = acc[i][2] * 0.125f; o.w = acc[i][3] * 0.125f;
        *(float4*)&crow[tx4] = o;
    }
}

// ---------------- softmax rows in-place (warp per row) ----------------
__global__ void softmax_kernel() {
    int row = blockIdx.x * 8 + (threadIdx.x >> 5);
    int lane = threadIdx.x & 31;
    int z = row >> 10;
    if (g_mask[z] == 0.f) return;
    float* p = g_scores + (size_t)row * S_;
    float v[32];
    float mx = -1e30f;
    #pragma unroll
    for (int i = 0; i < 32; i++) { v[i] = p[lane + (i << 5)]; mx = fmaxf(mx, v[i]); }
    #pragma unroll
    for (int o = 16; o > 0; o >>= 1) mx = fmaxf(mx, __shfl_xor_sync(0xffffffffu, mx, o));
    float sum = 0.f;
    #pragma unroll
    for (int i = 0; i < 32; i++) { v[i] = __expf(v[i] - mx); sum += v[i]; }
    #pragma unroll
    for (int o = 16; o > 0; o >>= 1) sum += __shfl_xor_sync(0xffffffffu, sum, o);
    float inv = 1.0f / sum;
    #pragma unroll
    for (int i = 0; i < 32; i++) p[lane + (i << 5)] = v[i] * inv;
}

// ---------------- ctx = P @ V per (b,h): NN gemm M=1024 N=64 K=1024 (zeros if masked) ----------------
__global__ void __launch_bounds__(256) pv_gemm() {
    int z = blockIdx.z;
    bool active = (g_mask[z] != 0.f);
    const float* A  = g_scores + (size_t)z * S_ * S_;
    const float* Bv = g_v + (size_t)z * S_ * D_;
    float* C = g_ctx + (size_t)z * S_ * D_;

    __shared__ float As[16][64];
    __shared__ float Bs[16][64];
    int tid = threadIdx.x;
    int tx4 = (tid & 15) << 2, ty4 = (tid >> 4) << 2;
    int m0 = blockIdx.y * 64;
    float acc[4][4] = {};
    if (active) {
        int ra = tid >> 2, ca = (tid & 3) << 2;
        int rb = tid >> 4, cb = (tid & 15) << 2;
        for (int k0 = 0; k0 < S_; k0 += 16) {
            float4 av = *(const float4*)&A[(size_t)(m0 + ra) * S_ + k0 + ca];
            As[ca + 0][ra] = av.x; As[ca + 1][ra] = av.y;
            As[ca + 2][ra] = av.z; As[ca + 3][ra] = av.w;
            *(float4*)&Bs[rb][cb] = *(const float4*)&Bv[(size_t)(k0 + rb) * D_ + cb];
            __syncthreads();
            TILE_MAC(As, Bs, ty4, tx4, acc)
            __syncthreads();
        }
    }
    #pragma unroll
    for (int i = 0; i < 4; i++) {
        float* crow = C + (size_t)(m0 + ty4 + i) * D_;
        float4 o = {acc[i][0], acc[i][1], acc[i][2], acc[i][3]};
        *(float4*)&crow[tx4] = o;
    }
}

// ---------------- x = ctx_flat @ Wo + bo + residual (gathered A loader) ----------------
__global__ void __launch_bounds__(256) out_gemm(
    const float* __restrict__ X, const float* __restrict__ Wo, const float* __restrict__ bo) {
    __shared__ float As[16][64];
    __shared__ float Bs[16][64];
    int tid = threadIdx.x;
    int tx4 = (tid & 15) << 2, ty4 = (tid >> 4) << 2;
    int m0 = blockIdx.y * 64;
    int n0 = blockIdx.x * 64;
    float acc[4][4] = {};
    int ra = tid >> 2, ca = (tid & 3) << 2;
    int rb = tid >> 4, cb = (tid & 15) << 2;
    int m = m0 + ra;
    int bb = m >> 10, s = m & (S_ - 1);
    for (int k0 = 0; k0 < HID; k0 += 16) {
        int kk = k0 + ca;
        int h = kk >> 6, d = kk & 63;
        float4 av = *(const float4*)&g_ctx[(((size_t)(bb * H_ + h) * S_) + s) * D_ + d];
        As[ca + 0][ra] = av.x; As[ca + 1][ra] = av.y;
        As[ca + 2][ra] = av.z; As[ca + 3][ra] = av.w;
        *(float4*)&Bs[rb][cb] = *(const float4*)&Wo[(size_t)(k0 + rb) * HID + n0 + cb];
        __syncthreads();
        TILE_MAC(As, Bs, ty4, tx4, acc)
        __syncthreads();
    }
    #pragma unroll
    for (int i = 0; i < 4; i++) {
        size_t roff = (size_t)(m0 + ty4 + i) * HID + n0 + tx4;
        float4 bo4 = *(const float4*)&bo[n0 + tx4];
        float4 r4  = *(const float4*)&X[roff];
        float4 o;
        o.x = acc[i][0] + bo4.x + r4.x;
        o.y = acc[i][1] + bo4.y + r4.y;
        o.z = acc[i][2] + bo4.z + r4.z;
        o.w = acc[i][3] + bo4.w + r4.w;
        *(float4*)&g_x[roff] = o;
    }
}

// ---------------- LayerNorm ----------------
__global__ void ln_kernel(const float* __restrict__ gam, const float* __restrict__ bet,
                          float* __restrict__ out) {
    __shared__ float red[256];
    int row = blockIdx.x;
    int tid = threadIdx.x;
    const float* xr = g_x + (size_t)row * HID;
    float v0 = xr[tid], v1 = xr[tid + 256], v2 = xr[tid + 512];
    red[tid] = v0 + v1 + v2;
    __syncthreads();
    #pragma unroll
    for (int o = 128; o > 0; o >>= 1) {
        if (tid < o) red[tid] += red[tid + o];
        __syncthreads();
    }
    float mu = red[0] * (1.0f / HID);
    __syncthreads();
    float d0 = v0 - mu, d1 = v1 - mu, d2 = v2 - mu;
    red[tid] = d0 * d0 + d1 * d1 + d2 * d2;
    __syncthreads();
    #pragma unroll
    for (int o = 128; o > 0; o >>= 1) {
        if (tid < o) red[tid] += red[tid + o];
        __syncthreads();
    }
    float inv = rsqrtf(red[0] * (1.0f / HID) + 1e-12f);
    float* orow = out + (size_t)row * HID;
    orow[tid]       = d0 * inv * gam[tid]       + bet[tid];
    orow[tid + 256] = d1 * inv * gam[tid + 256] + bet[tid + 256];
    orow[tid + 512] = d2 * inv * gam[tid + 512] + bet[tid + 512];
}

// ---------------- launch ----------------
extern "C" void kernel_launch(void* const* d_in, const int* in_sizes, int n_in,
                              void* d_out, int out_size) {
    const float* X  = (const float*)d_in[0];
    const float* Wq = (const float*)d_in[1];
    const float* bq = (const float*)d_in[2];
    const float* Wk = (const float*)d_in[3];
    const float* bk = (const float*)d_in[4];
    const float* Wv = (const float*)d_in[5];
    const float* bv = (const float*)d_in[6];
    const float* Wr = (const float*)d_in[7];
    const float* br = (const float*)d_in[8];
    const float* Wo = (const float*)d_in[9];
    const float* bo = (const float*)d_in[10];
    const float* lg = (const float*)d_in[11];
    const float* lb = (const float*)d_in[12];
    float* out = (float*)d_out;

    mean_partial_kernel<<<dim3(B_, 32), 256>>>(X);
    router_kernel<<<B_, 256>>>(Wr, br);
    qkv_gemm<<<dim3(HID / 64, NROWS / 64, 3), 256>>>(X, Wq, bq, Wk, bk, Wv, bv);
    score_gemm<<<dim3(S_ / 64, S_ / 64, NZ), 256>>>();
    softmax_kernel<<<(NZ * S_) / 8, 256>>>();
    pv_gemm<<<dim3(1, S_ / 64, NZ), 256>>>();
    out_gemm<<<dim3(HID / 64, NROWS / 64), 256>>>(X, Wo, bo);
    ln_kernel<<<NROWS, 256>>>(lg, lb, out);
}

// round 2
// speedup vs baseline: 2.1325x; 2.1325x over previous
#include <cuda_runtime.h>
#include <math.h>

#define B_   8
#define S_   1024
#define H_   12
#define D_   64
#define HID  768
#define KTOP 6
#define NROWS (B_ * S_)        // 8192
#define NZ    (B_ * H_)        // 96

typedef unsigned long long ull;

// ---------------- scratch ----------------
__device__ float g_rpart[B_ * 32 * HID];
__device__ float g_mask[NZ];
__device__ float g_q[NZ * S_ * D_];
__device__ float g_k[NZ * S_ * D_];
__device__ float g_v[NZ * S_ * D_];
__device__ float g_scores[100663296];              // 96 * 1024 * 1024
__device__ float g_xc[NROWS * HID];                // flat ctx [8192 x 768]
__device__ float g_x[NROWS * HID];                 // pre-LN activations

// ---------------- f32x2 helpers ----------------
__device__ __forceinline__ ull pk2(float lo, float hi) {
    ull r; asm("mov.b64 %0,{%1,%2};" : "=l"(r) : "f"(lo), "f"(hi)); return r;
}
__device__ __forceinline__ void upk2(ull v, float& lo, float& hi) {
    asm("mov.b64 {%0,%1},%2;" : "=f"(lo), "=f"(hi) : "l"(v));
}
__device__ __forceinline__ ull ffma2(ull a, ull b, ull c) {
    ull d; asm("fma.rn.f32x2 %0,%1,%2,%3;" : "=l"(d) : "l"(a), "l"(b), "l"(c)); return d;
}

// ---------------- stage 1: partial column sums ----------------
__global__ void mean_partial_kernel(const float* __restrict__ X) {
    int b = blockIdx.x, chunk = blockIdx.y, tid = threadIdx.x;
    const float* Xb = X + ((size_t)b * S_ + chunk * 32) * HID;
    #pragma unroll
    for (int j = 0; j < 3; j++) {
        int c = tid + j * 256;
        float s = 0.f;
        #pragma unroll 8
        for (int r = 0; r < 32; r++) s += Xb[r * HID + c];
        g_rpart[(b * 32 + chunk) * HID + c] = s;
    }
}

// ---------------- stage 2: router ----------------
__global__ void router_kernel(const float* __restrict__ Wr, const float* __restrict__ br) {
    __shared__ float rin[HID];
    __shared__ float logits[H_];
    int b = blockIdx.x, tid = threadIdx.x;
    #pragma unroll
    for (int j = 0; j < 3; j++) {
        int c = tid + j * 256;
        float s = 0.f;
        #pragma unroll
        for (int p = 0; p < 32; p++) s += g_rpart[(b * 32 + p) * HID + c];
        rin[c] = s * (1.0f / S_);
    }
    __syncthreads();
    int warp = tid >> 5, lane = tid & 31;
    for (int h = warp; h < H_; h += 8) {
        float s = 0.f;
        for (int c = lane; c < HID; c += 32) s += rin[c] * Wr[c * H_ + h];
        #pragma unroll
        for (int o = 16; o > 0; o >>= 1) s += __shfl_xor_sync(0xffffffffu, s, o);
        if (lane == 0) logits[h] = s + br[h];
    }
    __syncthreads();
    if (tid < H_) {
        float v = logits[tid];
        int rank = 0;
        #pragma unroll
        for (int j = 0; j < H_; j++) {
            float u = logits[j];
            if (u > v || (u == v && j < tid)) rank++;
        }
        g_mask[b * H_ + tid] = (rank < KTOP) ? 1.0f : 0.0f;
    }
}

// ---------------- 8x8 microtile MAC with f32x2 (col-paired) ----------------
// acc[8][4] of f32x2: rows i (0..3 -> ty4+i, 4..7 -> ty4+64+i-4),
// col-pairs jp: 0,1 -> cols tx4+0..3 ; 2,3 -> cols tx4+64..67
#define MAC_8x8(AS, BS, TY4, TX4, ACC)                                       \
    _Pragma("unroll")                                                         \
    for (int kk = 0; kk < 16; kk++) {                                         \
        float4 a0 = *(float4*)&AS[kk][TY4];                                   \
        float4 a1 = *(float4*)&AS[kk][TY4 + 64];                              \
        float4 b0 = *(float4*)&BS[kk][TX4];                                   \
        float4 b1 = *(float4*)&BS[kk][TX4 + 64];                              \
        ull bp0 = pk2(b0.x, b0.y), bp1 = pk2(b0.z, b0.w);                     \
        ull bp2 = pk2(b1.x, b1.y), bp3 = pk2(b1.z, b1.w);                     \
        float ar[8] = {a0.x, a0.y, a0.z, a0.w, a1.x, a1.y, a1.z, a1.w};       \
        _Pragma("unroll")                                                     \
        for (int i = 0; i < 8; i++) {                                         \
            ull ad = pk2(ar[i], ar[i]);                                       \
            ACC[i][0] = ffma2(ad, bp0, ACC[i][0]);                            \
            ACC[i][1] = ffma2(ad, bp1, ACC[i][1]);                            \
            ACC[i][2] = ffma2(ad, bp2, ACC[i][2]);                            \
            ACC[i][3] = ffma2(ad, bp3, ACC[i][3]);                            \
        }                                                                     \
    }

// A loader: row-major A[lda], tile rows m0..m0+127, k-cols k0..k0+15, transposed
#define LOAD_A_T(AS, Aptr, LDA, M0, K0)                                      \
    {                                                                         \
        int ar = tid >> 2, ac = (tid & 3) << 2;                               \
        float4 v0 = *(const float4*)&Aptr[(size_t)(M0 + ar) * LDA + K0 + ac]; \
        float4 v1 = *(const float4*)&Aptr[(size_t)(M0 + ar + 64) * LDA + K0 + ac]; \
        AS[ac + 0][ar] = v0.x; AS[ac + 1][ar] = v0.y;                         \
        AS[ac + 2][ar] = v0.z; AS[ac + 3][ar] = v0.w;                         \
        AS[ac + 0][ar + 64] = v1.x; AS[ac + 1][ar + 64] = v1.y;               \
        AS[ac + 2][ar + 64] = v1.z; AS[ac + 3][ar + 64] = v1.w;               \
    }

// B loader: row-major B[ldb], k-rows k0..k0+15, n-cols n0..n0+127
#define LOAD_B(BS, Bptr, LDB, K0, N0)                                        \
    {                                                                         \
        int br = tid >> 5, bc = (tid & 31) << 2;                              \
        *(float4*)&BS[br][bc]     = *(const float4*)&Bptr[(size_t)(K0 + br) * LDB + N0 + bc]; \
        *(float4*)&BS[br + 8][bc] = *(const float4*)&Bptr[(size_t)(K0 + br + 8) * LDB + N0 + bc]; \
    }

// ---------------- QKV projection ----------------
__global__ void __launch_bounds__(256, 2) qkv_gemm(
    const float* __restrict__ X,
    const float* __restrict__ Wq, const float* __restrict__ bq,
    const float* __restrict__ Wk, const float* __restrict__ bk,
    const float* __restrict__ Wv, const float* __restrict__ bv) {
    const float* W; const float* bias; float* out;
    int z = blockIdx.z;
    if (z == 0)      { W = Wq; bias = bq; out = g_q; }
    else if (z == 1) { W = Wk; bias = bk; out = g_k; }
    else             { W = Wv; bias = bv; out = g_v; }

    __shared__ float As[16][128];
    __shared__ float Bs[16][128];
    int tid = threadIdx.x;
    int tx4 = (tid & 15) << 2, ty4 = (tid >> 4) << 2;
    int m0 = blockIdx.y * 128;
    int n0 = blockIdx.x * 128;
    ull acc[8][4] = {};

    for (int k0 = 0; k0 < HID; k0 += 16) {
        LOAD_A_T(As, X, HID, m0, k0)
        LOAD_B(Bs, W, HID, k0, n0)
        __syncthreads();
        MAC_8x8(As, Bs, ty4, tx4, acc)
        __syncthreads();
    }

    int bb = m0 >> 10;
    int s0 = m0 & (S_ - 1);
    int h0 = n0 >> 6;                 // two heads: h0, h0+1
    float mk0 = g_mask[bb * H_ + h0];
    float mk1 = g_mask[bb * H_ + h0 + 1];
    float4 bias0 = *(const float4*)&bias[n0 + tx4];
    float4 bias1 = *(const float4*)&bias[n0 + 64 + tx4];
    #pragma unroll
    for (int i = 0; i < 8; i++) {
        int r = (i < 4) ? (ty4 + i) : (ty4 + 64 + i - 4);
        int s = s0 + r;
        float c0, c1, c2, c3;
        upk2(acc[i][0], c0, c1); upk2(acc[i][1], c2, c3);
        float4 o0 = { (c0 + bias0.x) * mk0, (c1 + bias0.y) * mk0,
                      (c2 + bias0.z) * mk0, (c3 + bias0.w) * mk0 };
        *(float4*)&out[(((size_t)(bb * H_ + h0) * S_ + s) << 6) + tx4] = o0;
        upk2(acc[i][2], c0, c1); upk2(acc[i][3], c2, c3);
        float4 o1 = { (c0 + bias1.x) * mk1, (c1 + bias1.y) * mk1,
                      (c2 + bias1.z) * mk1, (c3 + bias1.w) * mk1 };
        *(float4*)&out[(((size_t)(bb * H_ + h0 + 1) * S_ + s) << 6) + tx4] = o1;
    }
}

// ---------------- scores = Q Kt / 8 : NT gemm M=N=1024 K=64 ----------------
__global__ void __launch_bounds__(256, 2) score_gemm() {
    int z = blockIdx.z;
    if (g_mask[z] == 0.f) return;
    const float* A  = g_q + (size_t)z * S_ * D_;
    const float* Bk = g_k + (size_t)z * S_ * D_;
    float* C = g_scores + (size_t)z * S_ * S_;

    __shared__ float As[16][128];
    __shared__ float Bs[16][128];
    int tid = threadIdx.x;
    int tx4 = (tid & 15) << 2, ty4 = (tid >> 4) << 2;
    int m0 = blockIdx.y * 128;
    int n0 = blockIdx.x * 128;
    ull acc[8][4] = {};

    for (int k0 = 0; k0 < D_; k0 += 16) {
        LOAD_A_T(As, A, D_, m0, k0)
        LOAD_A_T(Bs, Bk, D_, n0, k0)       // K^T: transposed load, same as A
        __syncthreads();
        MAC_8x8(As, Bs, ty4, tx4, acc)
        __syncthreads();
    }
    #pragma unroll
    for (int i = 0; i < 8; i++) {
        int r = (i < 4) ? (ty4 + i) : (ty4 + 64 + i - 4);
        float* crow = C + (size_t)(m0 + r) * S_;
        float c0, c1, c2, c3;
        upk2(acc[i][0], c0, c1); upk2(acc[i][1], c2, c3);
        float4 o0 = { c0 * 0.125f, c1 * 0.125f, c2 * 0.125f, c3 * 0.125f };
        *(float4*)&crow[n0 + tx4] = o0;
        upk2(acc[i][2], c0, c1); upk2(acc[i][3], c2, c3);
        float4 o1 = { c0 * 0.125f, c1 * 0.125f, c2 * 0.125f, c3 * 0.125f };
        *(float4*)&crow[n0 + 64 + tx4] = o1;
    }
}

// ---------------- softmax in-place ----------------
__global__ void softmax_kernel() {
    int row = blockIdx.x * 8 + (threadIdx.x >> 5);
    int lane = threadIdx.x & 31;
    int z = row >> 10;
    if (g_mask[z] == 0.f) return;
    float* p = g_scores + (size_t)row * S_;
    float v[32];
    float mx = -1e30f;
    #pragma unroll
    for (int i = 0; i < 32; i++) { v[i] = p[lane + (i << 5)]; mx = fmaxf(mx, v[i]); }
    #pragma unroll
    for (int o = 16; o > 0; o >>= 1) mx = fmaxf(mx, __shfl_xor_sync(0xffffffffu, mx, o));
    float sum = 0.f;
    #pragma unroll
    for (int i = 0; i < 32; i++) { v[i] = __expf(v[i] - mx); sum += v[i]; }
    #pragma unroll
    for (int o = 16; o > 0; o >>= 1) sum += __shfl_xor_sync(0xffffffffu, sum, o);
    float inv = 1.0f / sum;
    #pragma unroll
    for (int i = 0; i < 32; i++) p[lane + (i << 5)] = v[i] * inv;
}

// ---------------- ctx = P @ V, written flat to g_xc [8192 x 768] ----------------
__global__ void __launch_bounds__(256, 2) pv_gemm() {
    int z = blockIdx.z;
    bool active = (g_mask[z] != 0.f);
    const float* A  = g_scores + (size_t)z * S_ * S_;
    const float* Bv = g_v + (size_t)z * S_ * D_;
    int bb = z / H_, h = z % H_;

    __shared__ float As[16][128];
    __shared__ float Bs[16][64];
    int tid = threadIdx.x;
    int tx4 = (tid & 15) << 2, ty4 = (tid >> 4) << 2;
    int m0 = blockIdx.y * 128;
    ull acc[8][2] = {};

    if (active) {
        for (int k0 = 0; k0 < S_; k0 += 16) {
            LOAD_A_T(As, A, S_, m0, k0)
            {
                int br = tid >> 4, bc = (tid & 15) << 2;
                *(float4*)&Bs[br][bc] = *(const float4*)&Bv[(size_t)(k0 + br) * D_ + bc];
            }
            __syncthreads();
            #pragma unroll
            for (int kk = 0; kk < 16; kk++) {
                float4 a0 = *(float4*)&As[kk][ty4];
                float4 a1 = *(float4*)&As[kk][ty4 + 64];
                float4 b0 = *(float4*)&Bs[kk][tx4];
                ull bp0 = pk2(b0.x, b0.y), bp1 = pk2(b0.z, b0.w);
                float ar[8] = {a0.x, a0.y, a0.z, a0.w, a1.x, a1.y, a1.z, a1.w};
                #pragma unroll
                for (int i = 0; i < 8; i++) {
                    ull ad = pk2(ar[i], ar[i]);
                    acc[i][0] = ffma2(ad, bp0, acc[i][0]);
                    acc[i][1] = ffma2(ad, bp1, acc[i][1]);
                }
            }
            __syncthreads();
        }
    }
    #pragma unroll
    for (int i = 0; i < 8; i++) {
        int r = (i < 4) ? (ty4 + i) : (ty4 + 64 + i - 4);
        float c0, c1, c2, c3;
        upk2(acc[i][0], c0, c1); upk2(acc[i][1], c2, c3);
        float4 o = {c0, c1, c2, c3};
        *(float4*)&g_xc[(size_t)(bb * S_ + m0 + r) * HID + h * D_ + tx4] = o;
    }
}

// ---------------- x = ctx @ Wo + bo + residual ----------------
__global__ void __launch_bounds__(256, 2) out_gemm(
    const float* __restrict__ X, const float* __restrict__ Wo, const float* __restrict__ bo) {
    __shared__ float As[16][128];
    __shared__ float Bs[16][128];
    int tid = threadIdx.x;
    int tx4 = (tid & 15) << 2, ty4 = (tid >> 4) << 2;
    int m0 = blockIdx.y * 128;
    int n0 = blockIdx.x * 128;
    ull acc[8][4] = {};

    for (int k0 = 0; k0 < HID; k0 += 16) {
        LOAD_A_T(As, g_xc, HID, m0, k0)
        LOAD_B(Bs, Wo, HID, k0, n0)
        __syncthreads();
        MAC_8x8(As, Bs, ty4, tx4, acc)
        __syncthreads();
    }
    float4 bo0 = *(const float4*)&bo[n0 + tx4];
    float4 bo1 = *(const float4*)&bo[n0 + 64 + tx4];
    #pragma unroll
    for (int i = 0; i < 8; i++) {
        int r = (i < 4) ? (ty4 + i) : (ty4 + 64 + i - 4);
        size_t roff0 = (size_t)(m0 + r) * HID + n0 + tx4;
        size_t roff1 = roff0 + 64;
        float c0, c1, c2, c3;
        upk2(acc[i][0], c0, c1); upk2(acc[i][1], c2, c3);
        float4 r4 = *(const float4*)&X[roff0];
        float4 o0 = { c0 + bo0.x + r4.x, c1 + bo0.y + r4.y,
                      c2 + bo0.z + r4.z, c3 + bo0.w + r4.w };
        *(float4*)&g_x[roff0] = o0;
        upk2(acc[i][2], c0, c1); upk2(acc[i][3], c2, c3);
        float4 r5 = *(const float4*)&X[roff1];
        float4 o1 = { c0 + bo1.x + r5.x, c1 + bo1.y + r5.y,
                      c2 + bo1.z + r5.z, c3 + bo1.w + r5.w };
        *(float4*)&g_x[roff1] = o1;
    }
}

// ---------------- LayerNorm ----------------
__global__ void ln_kernel(const float* __restrict__ gam, const float* __restrict__ bet,
                          float* __restrict__ out) {
    __shared__ float red[256];
    int row = blockIdx.x;
    int tid = threadIdx.x;
    const float* xr = g_x + (size_t)row * HID;
    float v0 = xr[tid], v1 = xr[tid + 256], v2 = xr[tid + 512];
    red[tid] = v0 + v1 + v2;
    __syncthreads();
    #pragma unroll
    for (int o = 128; o > 0; o >>= 1) {
        if (tid < o) red[tid] += red[tid + o];
        __syncthreads();
    }
    float mu = red[0] * (1.0f / HID);
    __syncthreads();
    float d0 = v0 - mu, d1 = v1 - mu, d2 = v2 - mu;
    red[tid] = d0 * d0 + d1 * d1 + d2 * d2;
    __syncthreads();
    #pragma unroll
    for (int o = 128; o > 0; o >>= 1) {
        if (tid < o) red[tid] += red[tid + o];
        __syncthreads();
    }
    float inv = rsqrtf(red[0] * (1.0f / HID) + 1e-12f);
    float* orow = out + (size_t)row * HID;
    orow[tid]       = d0 * inv * gam[tid]       + bet[tid];
    orow[tid + 256] = d1 * inv * gam[tid + 256] + bet[tid + 256];
    orow[tid + 512] = d2 * inv * gam[tid + 512] + bet[tid + 512];
}

// ---------------- launch ----------------
extern "C" void kernel_launch(void* const* d_in, const int* in_sizes, int n_in,
                              void* d_out, int out_size) {
    const float* X  = (const float*)d_in[0];
    const float* Wq = (const float*)d_in[1];
    const float* bq = (const float*)d_in[2];
    const float* Wk = (const float*)d_in[3];
    const float* bk = (const float*)d_in[4];
    const float* Wv = (const float*)d_in[5];
    const float* bv = (const float*)d_in[6];
    const float* Wr = (const float*)d_in[7];
    const float* br = (const float*)d_in[8];
    const float* Wo = (const float*)d_in[9];
    const float* bo = (const float*)d_in[10];
    const float* lg = (const float*)d_in[11];
    const float* lb = (const float*)d_in[12];
    float* out = (float*)d_out;

    mean_partial_kernel<<<dim3(B_, 32), 256>>>(X);
    router_kernel<<<B_, 256>>>(Wr, br);
    qkv_gemm<<<dim3(HID / 128, NROWS / 128, 3), 256>>>(X, Wq, bq, Wk, bk, Wv, bv);
    score_gemm<<<dim3(S_ / 128, S_ / 128, NZ), 256>>>();
    softmax_kernel<<<(NZ * S_) / 8, 256>>>();
    pv_gemm<<<dim3(1, S_ / 128, NZ), 256>>>();
    out_gemm<<<dim3(HID / 128, NROWS / 128), 256>>>(X, Wo, bo);
    ln_kernel<<<NROWS, 256>>>(lg, lb, out);
}

// round 4
// speedup vs baseline: 7.0041x; 3.2844x over previous
#include <cuda_runtime.h>
#include <cuda_bf16.h>
#include <math.h>

#define B_   8
#define S_   1024
#define H_   12
#define D_   64
#define HID  768
#define KTOP 6
#define NROWS (B_ * S_)        // 8192
#define NZ    (B_ * H_)        // 96

typedef unsigned int u32;
typedef __nv_bfloat16 bf16;

// ---------------- scratch ----------------
__device__ float g_rpart[B_ * 32 * HID];
__device__ float g_mask[NZ];
__device__ bf16  g_xb[NROWS * HID];                // X in bf16
__device__ bf16  g_wq[HID * HID];
__device__ bf16  g_wk[HID * HID];
__device__ bf16  g_wv[HID * HID];
__device__ bf16  g_wo[HID * HID];
__device__ bf16  g_q[NZ * S_ * D_];
__device__ bf16  g_k[NZ * S_ * D_];
__device__ bf16  g_v[NZ * S_ * D_];
__device__ bf16  g_sc[100663296];                  // 96*1024*1024 scores/probs (bf16)
__device__ bf16  g_xc[NROWS * HID];                // flat ctx bf16
__device__ float g_x[NROWS * HID];                 // pre-LN activations fp32

// ---------------- asm helpers ----------------
__device__ __forceinline__ u32 sptr(const void* p) {
    return (u32)__cvta_generic_to_shared(p);
}
#define CP16(d, s) asm volatile("cp.async.cg.shared.global [%0],[%1],16;\n" :: "r"(d), "l"(s))
#define CPCOMMIT() asm volatile("cp.async.commit_group;\n")
#define CPWAIT0()  asm volatile("cp.async.wait_group 0;\n")
#define CPWAIT1()  asm volatile("cp.async.wait_group 1;\n")

__device__ __forceinline__ void ldsm4(u32 (&r)[4], u32 a) {
    asm volatile("ldmatrix.sync.aligned.m8n8.x4.shared.b16 {%0,%1,%2,%3},[%4];"
                 : "=r"(r[0]), "=r"(r[1]), "=r"(r[2]), "=r"(r[3]) : "r"(a));
}
__device__ __forceinline__ void ldsm4t(u32 (&r)[4], u32 a) {
    asm volatile("ldmatrix.sync.aligned.m8n8.x4.trans.shared.b16 {%0,%1,%2,%3},[%4];"
                 : "=r"(r[0]), "=r"(r[1]), "=r"(r[2]), "=r"(r[3]) : "r"(a));
}
__device__ __forceinline__ void mma16816(float (&d)[4], const u32 (&a)[4], u32 b0, u32 b1) {
    asm volatile(
        "mma.sync.aligned.m16n8k16.row.col.f32.bf16.bf16.f32 "
        "{%0,%1,%2,%3},{%4,%5,%6,%7},{%8,%9},{%0,%1,%2,%3};"
        : "+f"(d[0]), "+f"(d[1]), "+f"(d[2]), "+f"(d[3])
        : "r"(a[0]), "r"(a[1]), "r"(a[2]), "r"(a[3]), "r"(b0), "r"(b1));
}

// ---------------- fp32 -> bf16 conversion ----------------
__global__ void cvt_kernel(const float* __restrict__ s, bf16* __restrict__ d, int n) {
    int i = (blockIdx.x * 256 + threadIdx.x) * 4;
    if (i < n) {
        float4 v = *(const float4*)(s + i);
        *(__nv_bfloat162*)(d + i)     = __floats2bfloat162_rn(v.x, v.y);
        *(__nv_bfloat162*)(d + i + 2) = __floats2bfloat162_rn(v.z, v.w);
    }
}

// ---------------- router path (fp32, exact) ----------------
__global__ void mean_partial_kernel(const float* __restrict__ X) {
    int b = blockIdx.x, chunk = blockIdx.y, tid = threadIdx.x;
    const float* Xb = X + ((size_t)b * S_ + chunk * 32) * HID;
    #pragma unroll
    for (int j = 0; j < 3; j++) {
        int c = tid + j * 256;
        float s = 0.f;
        #pragma unroll 8
        for (int r = 0; r < 32; r++) s += Xb[r * HID + c];
        g_rpart[(b * 32 + chunk) * HID + c] = s;
    }
}

__global__ void router_kernel(const float* __restrict__ Wr, const float* __restrict__ br) {
    __shared__ float rin[HID];
    __shared__ float logits[H_];
    int b = blockIdx.x, tid = threadIdx.x;
    #pragma unroll
    for (int j = 0; j < 3; j++) {
        int c = tid + j * 256;
        float s = 0.f;
        #pragma unroll
        for (int p = 0; p < 32; p++) s += g_rpart[(b * 32 + p) * HID + c];
        rin[c] = s * (1.0f / S_);
    }
    __syncthreads();
    int warp = tid >> 5, lane = tid & 31;
    for (int h = warp; h < H_; h += 8) {
        float s = 0.f;
        for (int c = lane; c < HID; c += 32) s += rin[c] * Wr[c * H_ + h];
        #pragma unroll
        for (int o = 16; o > 0; o >>= 1) s += __shfl_xor_sync(0xffffffffu, s, o);
        if (lane == 0) logits[h] = s + br[h];
    }
    __syncthreads();
    if (tid < H_) {
        float v = logits[tid];
        int rank = 0;
        #pragma unroll
        for (int j = 0; j < H_; j++) {
            float u = logits[j];
            if (u > v || (u == v && j < tid)) rank++;
        }
        g_mask[b * H_ + tid] = (rank < KTOP) ? 1.0f : 0.0f;
    }
}

// ============ QKV: C[8192,768] = Xb @ W, bias+mask epilogue, scatter bf16 ============
__global__ void __launch_bounds__(256, 2) qkv_gemm(
    const float* __restrict__ bq, const float* __restrict__ bk, const float* __restrict__ bv) {
    __shared__ bf16 As[2][128][56];
    __shared__ bf16 Bs[2][32][136];
    int z = blockIdx.z;
    const bf16* W = (z == 0) ? g_wq : (z == 1) ? g_wk : g_wv;
    const float* bias = (z == 0) ? bq : (z == 1) ? bk : bv;
    bf16* out = (z == 0) ? g_q : (z == 1) ? g_k : g_v;

    int tid = threadIdx.x, lane = tid & 31, wid = tid >> 5;
    int wm = (wid >> 2) * 64, wn = (wid & 3) * 32;
    int m0 = blockIdx.y * 128, n0 = blockIdx.x * 128;
    float acc[4][4][4] = {};

    int arow = tid >> 1, acol = (tid & 1) * 16;
    int brow = tid >> 3, bcol = (tid & 7) * 16;
    const bf16* Abase = g_xb + (size_t)(m0 + arow) * HID + acol;

    #define QKV_LOAD(KT, BUF)                                                  \
        {                                                                      \
            const bf16* Ag = Abase + (KT) * 32;                                \
            CP16(sptr(&As[BUF][arow][acol]), Ag);                              \
            CP16(sptr(&As[BUF][arow][acol + 8]), Ag + 8);                      \
            const bf16* Bg = W + (size_t)((KT) * 32 + brow) * HID + n0 + bcol; \
            CP16(sptr(&Bs[BUF][brow][bcol]), Bg);                              \
            CP16(sptr(&Bs[BUF][brow][bcol + 8]), Bg + 8);                      \
        }

    QKV_LOAD(0, 0) CPCOMMIT();
    for (int kt = 0; kt < 24; kt++) {
        int cur = kt & 1;
        if (kt < 23) { QKV_LOAD(kt + 1, cur ^ 1) CPCOMMIT(); CPWAIT1(); }
        else CPWAIT0();
        __syncthreads();
        #pragma unroll
        for (int kk = 0; kk < 2; kk++) {
            u32 a[4][4], bfr[2][4];
            #pragma unroll
            for (int mi = 0; mi < 4; mi++) {
                int r = wm + mi * 16 + (lane & 7) + ((lane >> 3) & 1) * 8;
                int c = kk * 16 + (lane >> 4) * 8;
                ldsm4(a[mi], sptr(&As[cur][r][c]));
            }
            #pragma unroll
            for (int nj = 0; nj < 2; nj++) {
                int rk = kk * 16 + (lane & 7) + ((lane >> 3) & 1) * 8;
                int cn = wn + nj * 16 + (lane >> 4) * 8;
                ldsm4t(bfr[nj], sptr(&Bs[cur][rk][cn]));
            }
            #pragma unroll
            for (int mi = 0; mi < 4; mi++)
                #pragma unroll
                for (int jn = 0; jn < 4; jn++)
                    mma16816(acc[mi][jn], a[mi], bfr[jn >> 1][(jn & 1) * 2], bfr[jn >> 1][(jn & 1) * 2 + 1]);
        }
        __syncthreads();
    }

    int bb = m0 >> 10;
    #pragma unroll
    for (int mi = 0; mi < 4; mi++) {
        int r0 = m0 + wm + mi * 16 + (lane >> 2);
        int s0 = r0 & (S_ - 1);
        #pragma unroll
        for (int jn = 0; jn < 4; jn++) {
            int co = wn + jn * 8 + (lane & 3) * 2;
            int head = (n0 + co) >> 6;
            int d = (n0 + co) & 63;
            float mk = g_mask[bb * H_ + head];
            float b0f = bias[n0 + co], b1f = bias[n0 + co + 1];
            float c0 = (acc[mi][jn][0] + b0f) * mk, c1 = (acc[mi][jn][1] + b1f) * mk;
            float c2 = (acc[mi][jn][2] + b0f) * mk, c3 = (acc[mi][jn][3] + b1f) * mk;
            size_t base = ((size_t)(bb * H_ + head) * S_ + s0) * D_ + d;
            *(__nv_bfloat162*)&out[base] = __floats2bfloat162_rn(c0, c1);
            *(__nv_bfloat162*)&out[base + 8 * D_] = __floats2bfloat162_rn(c2, c3);
        }
    }
}

// ============ scores = Q @ K^T / 8 : NT, M=N=1024, K=64, single k-iter ============
__global__ void __launch_bounds__(256, 2) score_gemm() {
    int z = blockIdx.z;
    if (g_mask[z] == 0.f) return;
    __shared__ bf16 As[128][72];
    __shared__ bf16 Bs[128][72];
    const bf16* Q  = g_q + ((size_t)z << 16);
    const bf16* Km = g_k + ((size_t)z << 16);

    int tid = threadIdx.x, lane = tid & 31, wid = tid >> 5;
    int wm = (wid >> 2) * 64, wn = (wid & 3) * 32;
    int m0 = blockIdx.y * 128, n0 = blockIdx.x * 128;
    float acc[4][4][4] = {};

    int arow = tid >> 1, acol = (tid & 1) * 32;
    {
        const bf16* Ag = Q + (size_t)(m0 + arow) * D_ + acol;
        CP16(sptr(&As[arow][acol]), Ag);
        CP16(sptr(&As[arow][acol + 8]), Ag + 8);
        CP16(sptr(&As[arow][acol + 16]), Ag + 16);
        CP16(sptr(&As[arow][acol + 24]), Ag + 24);
        const bf16* Bg = Km + (size_t)(n0 + arow) * D_ + acol;
        CP16(sptr(&Bs[arow][acol]), Bg);
        CP16(sptr(&Bs[arow][acol + 8]), Bg + 8);
        CP16(sptr(&Bs[arow][acol + 16]), Bg + 16);
        CP16(sptr(&Bs[arow][acol + 24]), Bg + 24);
    }
    CPCOMMIT(); CPWAIT0();
    __syncthreads();

    #pragma unroll
    for (int kk = 0; kk < 4; kk++) {
        u32 a[4][4], bfr[2][4];
        #pragma unroll
        for (int mi = 0; mi < 4; mi++) {
            int r = wm + mi * 16 + (lane & 7) + ((lane >> 3) & 1) * 8;
            int c = kk * 16 + (lane >> 4) * 8;
            ldsm4(a[mi], sptr(&As[r][c]));
        }
        #pragma unroll
        for (int nj = 0; nj < 2; nj++) {
            int rn = wn + nj * 16 + (lane & 7) + (lane >> 4) * 8;
            int ck = kk * 16 + ((lane >> 3) & 1) * 8;
            ldsm4(bfr[nj], sptr(&Bs[rn][ck]));
        }
        #pragma unroll
        for (int mi = 0; mi < 4; mi++)
            #pragma unroll
            for (int jn = 0; jn < 4; jn++)
                mma16816(acc[mi][jn], a[mi], bfr[jn >> 1][(jn & 1) * 2], bfr[jn >> 1][(jn & 1) * 2 + 1]);
    }

    bf16* C = g_sc + ((size_t)z << 20);
    #pragma unroll
    for (int mi = 0; mi < 4; mi++) {
        int r0 = m0 + wm + mi * 16 + (lane >> 2);
        #pragma unroll
        for (int jn = 0; jn < 4; jn++) {
            int col = n0 + wn + jn * 8 + (lane & 3) * 2;
            *(__nv_bfloat162*)&C[(size_t)r0 * S_ + col] =
                __floats2bfloat162_rn(acc[mi][jn][0] * 0.125f, acc[mi][jn][1] * 0.125f);
            *(__nv_bfloat162*)&C[(size_t)(r0 + 8) * S_ + col] =
                __floats2bfloat162_rn(acc[mi][jn][2] * 0.125f, acc[mi][jn][3] * 0.125f);
        }
    }
}

// ---------------- softmax in-place on bf16 scores ----------------
__global__ void softmax_kernel() {
    int row = blockIdx.x * 8 + (threadIdx.x >> 5);
    int lane = threadIdx.x & 31;
    int z = row >> 10;
    if (g_mask[z] == 0.f) return;
    bf16* p = g_sc + ((size_t)row << 10);
    float v[32];
    float mx = -1e30f;
    #pragma unroll
    for (int i = 0; i < 32; i++) { v[i] = __bfloat162float(p[lane + (i << 5)]); mx = fmaxf(mx, v[i]); }
    #pragma unroll
    for (int o = 16; o > 0; o >>= 1) mx = fmaxf(mx, __shfl_xor_sync(0xffffffffu, mx, o));
    float sum = 0.f;
    #pragma unroll
    for (int i = 0; i < 32; i++) { v[i] = __expf(v[i] - mx); sum += v[i]; }
    #pragma unroll
    for (int o = 16; o > 0; o >>= 1) sum += __shfl_xor_sync(0xffffffffu, sum, o);
    float inv = 1.0f / sum;
    #pragma unroll
    for (int i = 0; i < 32; i++) p[lane + (i << 5)] = __float2bfloat16(v[i] * inv);
}

// ============ ctx = P @ V : NN, M=1024, N=64, K=1024; write flat bf16 ============
__global__ void __launch_bounds__(256, 2) pv_gemm() {
    int z = blockIdx.z;
    bool active = (g_mask[z] != 0.f);
    __shared__ bf16 As[2][128][56];
    __shared__ bf16 Bs[2][32][72];
    const bf16* P = g_sc + ((size_t)z << 20);
    const bf16* V = g_v + ((size_t)z << 16);
    int bb = z / H_, h = z % H_;

    int tid = threadIdx.x, lane = tid & 31, wid = tid >> 5;
    int wm = (wid >> 1) * 32, wn = (wid & 1) * 32;
    int m0 = blockIdx.y * 128;
    float acc[2][4][4] = {};

    int arow = tid >> 1, acol = (tid & 1) * 16;
    int brow = tid >> 3, bcol = (tid & 7) * 8;
    const bf16* Abase = P + (size_t)(m0 + arow) * S_ + acol;

    #define PV_LOAD(KT, BUF)                                              \
        {                                                                 \
            const bf16* Ag = Abase + (KT) * 32;                           \
            CP16(sptr(&As[BUF][arow][acol]), Ag);                         \
            CP16(sptr(&As[BUF][arow][acol + 8]), Ag + 8);                 \
            const bf16* Bg = V + (size_t)((KT) * 32 + brow) * D_ + bcol;  \
            CP16(sptr(&Bs[BUF][brow][bcol]), Bg);                         \
        }

    if (active) {
        PV_LOAD(0, 0) CPCOMMIT();
        for (int kt = 0; kt < 32; kt++) {
            int cur = kt & 1;
            if (kt < 31) { PV_LOAD(kt + 1, cur ^ 1) CPCOMMIT(); CPWAIT1(); }
            else CPWAIT0();
            __syncthreads();
            #pragma unroll
            for (int kk = 0; kk < 2; kk++) {
                u32 a[2][4], bfr[2][4];
                #pragma unroll
                for (int mi = 0; mi < 2; mi++) {
                    int r = wm + mi * 16 + (lane & 7) + ((lane >> 3) & 1) * 8;
                    int c = kk * 16 + (lane >> 4) * 8;
                    ldsm4(a[mi], sptr(&As[cur][r][c]));
                }
                #pragma unroll
                for (int nj = 0; nj < 2; nj++) {
                    int rk = kk * 16 + (lane & 7) + ((lane >> 3) & 1) * 8;
                    int cn = wn + nj * 16 + (lane >> 4) * 8;
                    ldsm4t(bfr[nj], sptr(&Bs[cur][rk][cn]));
                }
                #pragma unroll
                for (int mi = 0; mi < 2; mi++)
                    #pragma unroll
                    for (int jn = 0; jn < 4; jn++)
                        mma16816(acc[mi][jn], a[mi], bfr[jn >> 1][(jn & 1) * 2], bfr[jn >> 1][(jn & 1) * 2 + 1]);
            }
            __syncthreads();
        }
    }
    #pragma unroll
    for (int mi = 0; mi < 2; mi++) {
        int r0 = m0 + wm + mi * 16 + (lane >> 2);
        #pragma unroll
        for (int jn = 0; jn < 4; jn++) {
            int co = wn + jn * 8 + (lane & 3) * 2;
            size_t base = (size_t)(bb * S_ + r0) * HID + h * D_ + co;
            *(__nv_bfloat162*)&g_xc[base] = __floats2bfloat162_rn(acc[mi][jn][0], acc[mi][jn][1]);
            *(__nv_bfloat162*)&g_xc[base + 8 * HID] = __floats2bfloat162_rn(acc[mi][jn][2], acc[mi][jn][3]);
        }
    }
}

// ============ x = ctx @ Wo + bo + residual (fp32 out) ============
__global__ void __launch_bounds__(256, 2) out_gemm(
    const float* __restrict__ X, const float* __restrict__ bo) {
    __shared__ bf16 As[2][128][56];
    __shared__ bf16 Bs[2][32][136];
    int tid = threadIdx.x, lane = tid & 31, wid = tid >> 5;
    int wm = (wid >> 2) * 64, wn = (wid & 3) * 32;
    int m0 = blockIdx.y * 128, n0 = blockIdx.x * 128;
    float acc[4][4][4] = {};

    int arow = tid >> 1, acol = (tid & 1) * 16;
    int brow = tid >> 3, bcol = (tid & 7) * 16;
    const bf16* Abase = g_xc + (size_t)(m0 + arow) * HID + acol;

    #define OUT_LOAD(KT, BUF)                                                      \
        {                                                                          \
            const bf16* Ag = Abase + (KT) * 32;                                    \
            CP16(sptr(&As[BUF][arow][acol]), Ag);                                  \
            CP16(sptr(&As[BUF][arow][acol + 8]), Ag + 8);                          \
            const bf16* Bg = g_wo + (size_t)((KT) * 32 + brow) * HID + n0 + bcol;  \
            CP16(sptr(&Bs[BUF][brow][bcol]), Bg);                                  \
            CP16(sptr(&Bs[BUF][brow][bcol + 8]), Bg + 8);                          \
        }

    OUT_LOAD(0, 0) CPCOMMIT();
    for (int kt = 0; kt < 24; kt++) {
        int cur = kt & 1;
        if (kt < 23) { OUT_LOAD(kt + 1, cur ^ 1) CPCOMMIT(); CPWAIT1(); }
        else CPWAIT0();
        __syncthreads();
        #pragma unroll
        for (int kk = 0; kk < 2; kk++) {
            u32 a[4][4], bfr[2][4];
            #pragma unroll
            for (int mi = 0; mi < 4; mi++) {
                int r = wm + mi * 16 + (lane & 7) + ((lane >> 3) & 1) * 8;
                int c = kk * 16 + (lane >> 4) * 8;
                ldsm4(a[mi], sptr(&As[cur][r][c]));
            }
            #pragma unroll
            for (int nj = 0; nj < 2; nj++) {
                int rk = kk * 16 + (lane & 7) + ((lane >> 3) & 1) * 8;
                int cn = wn + nj * 16 + (lane >> 4) * 8;
                ldsm4t(bfr[nj], sptr(&Bs[cur][rk][cn]));
            }
            #pragma unroll
            for (int mi = 0; mi < 4; mi++)
                #pragma unroll
                for (int jn = 0; jn < 4; jn++)
                    mma16816(acc[mi][jn], a[mi], bfr[jn >> 1][(jn & 1) * 2], bfr[jn >> 1][(jn & 1) * 2 + 1]);
        }
        __syncthreads();
    }
    #pragma unroll
    for (int mi = 0; mi < 4; mi++) {
        int r0 = m0 + wm + mi * 16 + (lane >> 2);
        #pragma unroll
        for (int jn = 0; jn < 4; jn++) {
            int col = n0 + wn + jn * 8 + (lane & 3) * 2;
            size_t off0 = (size_t)r0 * HID + col;
            size_t off1 = off0 + 8 * HID;
            float2 x0 = *(const float2*)&X[off0];
            float2 x1 = *(const float2*)&X[off1];
            float b0f = bo[col], b1f = bo[col + 1];
            float2 o0 = { acc[mi][jn][0] + b0f + x0.x, acc[mi][jn][1] + b1f + x0.y };
            float2 o1 = { acc[mi][jn][2] + b0f + x1.x, acc[mi][jn][3] + b1f + x1.y };
            *(float2*)&g_x[off0] = o0;
            *(float2*)&g_x[off1] = o1;
        }
    }
}

// ---------------- LayerNorm (fp32) ----------------
__global__ void ln_kernel(const float* __restrict__ gam, const float* __restrict__ bet,
                          float* __restrict__ out) {
    __shared__ float red[256];
    int row = blockIdx.x;
    int tid = threadIdx.x;
    const float* xr = g_x + (size_t)row * HID;
    float v0 = xr[tid], v1 = xr[tid + 256], v2 = xr[tid + 512];
    red[tid] = v0 + v1 + v2;
    __syncthreads();
    #pragma unroll
    for (int o = 128; o > 0; o >>= 1) {
        if (tid < o) red[tid] += red[tid + o];
        __syncthreads();
    }
    float mu = red[0] * (1.0f / HID);
    __syncthreads();
    float d0 = v0 - mu, d1 = v1 - mu, d2 = v2 - mu;
    red[tid] = d0 * d0 + d1 * d1 + d2 * d2;
    __syncthreads();
    #pragma unroll
    for (int o = 128; o > 0; o >>= 1) {
        if (tid < o) red[tid] += red[tid + o];
        __syncthreads();
    }
    float inv = rsqrtf(red[0] * (1.0f / HID) + 1e-12f);
    float* orow = out + (size_t)row * HID;
    orow[tid]       = d0 * inv * gam[tid]       + bet[tid];
    orow[tid + 256] = d1 * inv * gam[tid + 256] + bet[tid + 256];
    orow[tid + 512] = d2 * inv * gam[tid + 512] + bet[tid + 512];
}

// ---------------- launch ----------------
extern "C" void kernel_launch(void* const* d_in, const int* in_sizes, int n_in,
                              void* d_out, int out_size) {
    const float* X  = (const float*)d_in[0];
    const float* Wq = (const float*)d_in[1];
    const float* bq = (const float*)d_in[2];
    const float* Wk = (const float*)d_in[3];
    const float* bk = (const float*)d_in[4];
    const float* Wv = (const float*)d_in[5];
    const float* bv = (const float*)d_in[6];
    const float* Wr = (const float*)d_in[7];
    const float* br = (const float*)d_in[8];
    const float* Wo = (const float*)d_in[9];
    const float* bo = (const float*)d_in[10];
    const float* lg = (const float*)d_in[11];
    const float* lb = (const float*)d_in[12];
    float* out = (float*)d_out;

    bf16 *dxb, *dwq, *dwk, *dwv, *dwo;
    cudaGetSymbolAddress((void**)&dxb, g_xb);
    cudaGetSymbolAddress((void**)&dwq, g_wq);
    cudaGetSymbolAddress((void**)&dwk, g_wk);
    cudaGetSymbolAddress((void**)&dwv, g_wv);
    cudaGetSymbolAddress((void**)&dwo, g_wo);

    const int NX = NROWS * HID;     // 6291456
    const int NW = HID * HID;       // 589824
    cvt_kernel<<<NX / 1024, 256>>>(X, dxb, NX);
    cvt_kernel<<<NW / 1024, 256>>>(Wq, dwq, NW);
    cvt_kernel<<<NW / 1024, 256>>>(Wk, dwk, NW);
    cvt_kernel<<<NW / 1024, 256>>>(Wv, dwv, NW);
    cvt_kernel<<<NW / 1024, 256>>>(Wo, dwo, NW);

    mean_partial_kernel<<<dim3(B_, 32), 256>>>(X);
    router_kernel<<<B_, 256>>>(Wr, br);

    qkv_gemm<<<dim3(HID / 128, NROWS / 128, 3), 256>>>(bq, bk, bv);
    score_gemm<<<dim3(S_ / 128, S_ / 128, NZ), 256>>>();
    softmax_kernel<<<(NZ * S_) / 8, 256>>>();
    pv_gemm<<<dim3(1, S_ / 128, NZ), 256>>>();
    out_gemm<<<dim3(HID / 128, NROWS / 128), 256>>>(X, bo);
    ln_kernel<<<NROWS, 256>>>(lg, lb, out);
}

// round 6
// speedup vs baseline: 8.8735x; 1.2669x over previous
#include <cuda_runtime.h>
#include <cuda_bf16.h>
#include <math.h>

#define B_   8
#define S_   1024
#define H_   12
#define D_   64
#define HID  768
#define KTOP 6
#define NROWS (B_ * S_)        // 8192
#define NZ    (B_ * H_)        // 96

typedef unsigned int u32;
typedef __nv_bfloat16 bf16;

// ---------------- scratch ----------------
__device__ float g_rpart[B_ * 32 * HID];
__device__ float g_mask[NZ];
__device__ bf16  g_xb[NROWS * HID];                // X in bf16
__device__ bf16  g_wq[HID * HID];
__device__ bf16  g_wk[HID * HID];
__device__ bf16  g_wv[HID * HID];
__device__ bf16  g_wo[HID * HID];
__device__ bf16  g_q[NZ * S_ * D_];                // Q pre-scaled by 0.125
__device__ bf16  g_k[NZ * S_ * D_];
__device__ bf16  g_v[NZ * S_ * D_];
__device__ bf16  g_xc[NROWS * HID];                // flat ctx bf16
__device__ float g_x[NROWS * HID];                 // pre-LN activations fp32

// ---------------- asm helpers ----------------
__device__ __forceinline__ u32 sptr(const void* p) {
    return (u32)__cvta_generic_to_shared(p);
}
#define CP16(d, s) asm volatile("cp.async.cg.shared.global [%0],[%1],16;\n" :: "r"(d), "l"(s))
#define CPCOMMIT() asm volatile("cp.async.commit_group;\n")
#define CPWAIT0()  asm volatile("cp.async.wait_group 0;\n")
#define CPWAIT1()  asm volatile("cp.async.wait_group 1;\n")

__device__ __forceinline__ void ldsm4(u32 (&r)[4], u32 a) {
    asm volatile("ldmatrix.sync.aligned.m8n8.x4.shared.b16 {%0,%1,%2,%3},[%4];"
                 : "=r"(r[0]), "=r"(r[1]), "=r"(r[2]), "=r"(r[3]) : "r"(a));
}
__device__ __forceinline__ void ldsm4t(u32 (&r)[4], u32 a) {
    asm volatile("ldmatrix.sync.aligned.m8n8.x4.trans.shared.b16 {%0,%1,%2,%3},[%4];"
                 : "=r"(r[0]), "=r"(r[1]), "=r"(r[2]), "=r"(r[3]) : "r"(a));
}
__device__ __forceinline__ void mma16816(float (&d)[4], const u32 (&a)[4], u32 b0, u32 b1) {
    asm volatile(
        "mma.sync.aligned.m16n8k16.row.col.f32.bf16.bf16.f32 "
        "{%0,%1,%2,%3},{%4,%5,%6,%7},{%8,%9},{%0,%1,%2,%3};"
        : "+f"(d[0]), "+f"(d[1]), "+f"(d[2]), "+f"(d[3])
        : "r"(a[0]), "r"(a[1]), "r"(a[2]), "r"(a[3]), "r"(b0), "r"(b1));
}
__device__ __forceinline__ u32 pkbf(float x, float y) {
    __nv_bfloat162 t = __floats2bfloat162_rn(x, y);
    return *(u32*)&t;
}

// ---------------- fp32 -> bf16 conversion (weights) ----------------
__global__ void cvt_kernel(const float* __restrict__ s, bf16* __restrict__ d, int n) {
    int i = (blockIdx.x * 256 + threadIdx.x) * 4;
    if (i < n) {
        float4 v = *(const float4*)(s + i);
        *(__nv_bfloat162*)(d + i)     = __floats2bfloat162_rn(v.x, v.y);
        *(__nv_bfloat162*)(d + i + 2) = __floats2bfloat162_rn(v.z, v.w);
    }
}

// ---------------- router path (fp32, exact) + X bf16 conversion ----------------
__global__ void mean_partial_kernel(const float* __restrict__ X) {
    int b = blockIdx.x, chunk = blockIdx.y, tid = threadIdx.x;
    size_t row0 = (size_t)b * S_ + chunk * 32;
    const float* Xb = X + row0 * HID;
    bf16* Ob = g_xb + row0 * HID;
    #pragma unroll
    for (int j = 0; j < 3; j++) {
        int c = tid + j * 256;
        float s = 0.f;
        #pragma unroll 8
        for (int r = 0; r < 32; r++) {
            float v = Xb[r * HID + c];
            s += v;
            Ob[r * HID + c] = __float2bfloat16(v);
        }
        g_rpart[(b * 32 + chunk) * HID + c] = s;
    }
}

__global__ void router_kernel(const float* __restrict__ Wr, const float* __restrict__ br) {
    __shared__ float rin[HID];
    __shared__ float logits[H_];
    int b = blockIdx.x, tid = threadIdx.x;
    #pragma unroll
    for (int j = 0; j < 3; j++) {
        int c = tid + j * 256;
        float s = 0.f;
        #pragma unroll
        for (int p = 0; p < 32; p++) s += g_rpart[(b * 32 + p) * HID + c];
        rin[c] = s * (1.0f / S_);
    }
    __syncthreads();
    int warp = tid >> 5, lane = tid & 31;
    for (int h = warp; h < H_; h += 8) {
        float s = 0.f;
        for (int c = lane; c < HID; c += 32) s += rin[c] * Wr[c * H_ + h];
        #pragma unroll
        for (int o = 16; o > 0; o >>= 1) s += __shfl_xor_sync(0xffffffffu, s, o);
        if (lane == 0) logits[h] = s + br[h];
    }
    __syncthreads();
    if (tid < H_) {
        float v = logits[tid];
        int rank = 0;
        #pragma unroll
        for (int j = 0; j < H_; j++) {
            float u = logits[j];
            if (u > v || (u == v && j < tid)) rank++;
        }
        g_mask[b * H_ + tid] = (rank < KTOP) ? 1.0f : 0.0f;
    }
}

// ============ QKV: C[8192,768] = Xb @ W, bias+mask epilogue, scatter bf16 ============
__global__ void __launch_bounds__(256, 2) qkv_gemm(
    const float* __restrict__ bq, const float* __restrict__ bk, const float* __restrict__ bv) {
    __shared__ bf16 As[2][128][56];
    __shared__ bf16 Bs[2][32][136];
    int z = blockIdx.z;
    const bf16* W = (z == 0) ? g_wq : (z == 1) ? g_wk : g_wv;
    const float* bias = (z == 0) ? bq : (z == 1) ? bk : bv;
    bf16* out = (z == 0) ? g_q : (z == 1) ? g_k : g_v;
    float qscale = (z == 0) ? 0.125f : 1.0f;       // fold 1/sqrt(D) into Q

    int tid = threadIdx.x, lane = tid & 31, wid = tid >> 5;
    int wm = (wid >> 2) * 64, wn = (wid & 3) * 32;
    int m0 = blockIdx.y * 128, n0 = blockIdx.x * 128;
    float acc[4][4][4] = {};

    int arow = tid >> 1, acol = (tid & 1) * 16;
    int brow = tid >> 3, bcol = (tid & 7) * 16;
    const bf16* Abase = g_xb + (size_t)(m0 + arow) * HID + acol;

    #define QKV_LOAD(KT, BUF)                                                  \
        {                                                                      \
            const bf16* Ag = Abase + (KT) * 32;                                \
            CP16(sptr(&As[BUF][arow][acol]), Ag);                              \
            CP16(sptr(&As[BUF][arow][acol + 8]), Ag + 8);                      \
            const bf16* Bg = W + (size_t)((KT) * 32 + brow) * HID + n0 + bcol; \
            CP16(sptr(&Bs[BUF][brow][bcol]), Bg);                              \
            CP16(sptr(&Bs[BUF][brow][bcol + 8]), Bg + 8);                      \
        }

    QKV_LOAD(0, 0) CPCOMMIT();
    for (int kt = 0; kt < 24; kt++) {
        int cur = kt & 1;
        if (kt < 23) { QKV_LOAD(kt + 1, cur ^ 1) CPCOMMIT(); CPWAIT1(); }
        else CPWAIT0();
        __syncthreads();
        #pragma unroll
        for (int kk = 0; kk < 2; kk++) {
            u32 a[4][4], bfr[2][4];
            #pragma unroll
            for (int mi = 0; mi < 4; mi++) {
                int r = wm + mi * 16 + (lane & 7) + ((lane >> 3) & 1) * 8;
                int c = kk * 16 + (lane >> 4) * 8;
                ldsm4(a[mi], sptr(&As[cur][r][c]));
            }
            #pragma unroll
            for (int nj = 0; nj < 2; nj++) {
                int rk = kk * 16 + (lane & 7) + ((lane >> 3) & 1) * 8;
                int cn = wn + nj * 16 + (lane >> 4) * 8;
                ldsm4t(bfr[nj], sptr(&Bs[cur][rk][cn]));
            }
            #pragma unroll
            for (int mi = 0; mi < 4; mi++)
                #pragma unroll
                for (int jn = 0; jn < 4; jn++)
                    mma16816(acc[mi][jn], a[mi], bfr[jn >> 1][(jn & 1) * 2], bfr[jn >> 1][(jn & 1) * 2 + 1]);
        }
        __syncthreads();
    }

    int bb = m0 >> 10;
    #pragma unroll
    for (int mi = 0; mi < 4; mi++) {
        int r0 = m0 + wm + mi * 16 + (lane >> 2);
        int s0 = r0 & (S_ - 1);
        #pragma unroll
        for (int jn = 0; jn < 4; jn++) {
            int co = wn + jn * 8 + (lane & 3) * 2;
            int head = (n0 + co) >> 6;
            int d = (n0 + co) & 63;
            float mk = g_mask[bb * H_ + head] * qscale;
            float b0f = bias[n0 + co], b1f = bias[n0 + co + 1];
            float c0 = (acc[mi][jn][0] + b0f) * mk, c1 = (acc[mi][jn][1] + b1f) * mk;
            float c2 = (acc[mi][jn][2] + b0f) * mk, c3 = (acc[mi][jn][3] + b1f) * mk;
            size_t base = ((size_t)(bb * H_ + head) * S_ + s0) * D_ + d;
            *(__nv_bfloat162*)&out[base] = __floats2bfloat162_rn(c0, c1);
            *(__nv_bfloat162*)&out[base + 8 * D_] = __floats2bfloat162_rn(c2, c3);
        }
    }
}

// ============ Flash attention: scores+softmax+PV fused, per (b,h) ============
// smem layout (rows of [72] bf16): Q rows 0-127, K bufs at 128+buf*128, V at 384+buf*128
#define FLASH_SMEM (640 * 72 * 2)

__global__ void __launch_bounds__(256, 1) flash_kernel() {
    extern __shared__ bf16 fsm[];
    bf16 (*SM)[72] = (bf16(*)[72])fsm;
    int z = blockIdx.y;
    int m0 = blockIdx.x * 128;
    int bb = z / H_, h = z % H_;
    int tid = threadIdx.x, lane = tid & 31, wid = tid >> 5;

    if (g_mask[z] == 0.f) {
        // zero-fill ctx tile (128 x 64) so out_gemm sees zeros
        #pragma unroll
        for (int i = tid; i < 2048; i += 256) {
            int row = i >> 4, c4 = (i & 15) << 2;
            *(uint2*)&g_xc[(size_t)(bb * S_ + m0 + row) * HID + h * D_ + c4] = make_uint2(0u, 0u);
        }
        return;
    }

    const bf16* Qg = g_q + ((size_t)z << 16);
    const bf16* Kg = g_k + ((size_t)z << 16);
    const bf16* Vg = g_v + ((size_t)z << 16);

    int arow = tid >> 1, acol = (tid & 1) << 5;    // 2 threads/row, 32 cols each

    #define LD_ROW128(DST, GP)                                        \
        {                                                             \
            u32 d = sptr(&SM[(DST) + arow][acol]);                    \
            const bf16* s = (GP) + (size_t)arow * D_ + acol;          \
            CP16(d, s); CP16(d + 16, s + 8);                          \
            CP16(d + 32, s + 16); CP16(d + 48, s + 24);               \
        }

    LD_ROW128(0, Qg + (size_t)m0 * D_)
    LD_ROW128(128, Kg)
    LD_ROW128(384, Vg)
    CPCOMMIT();
    LD_ROW128(256, Kg + (size_t)128 * D_)
    LD_ROW128(512, Vg + (size_t)128 * D_)
    CPCOMMIT();
    CPWAIT1();
    __syncthreads();

    // Q fragments (register-resident, loaded once)
    u32 qa[4][4];
    {
        int qr = wid * 16 + (lane & 7) + ((lane >> 3) & 1) * 8;
        int qc = (lane >> 4) * 8;
        #pragma unroll
        for (int kc = 0; kc < 4; kc++)
            ldsm4(qa[kc], sptr(&SM[qr][kc * 16 + qc]));
    }

    float mrow0 = -1e30f, mrow1 = -1e30f;
    float lsum0 = 0.f, lsum1 = 0.f;
    float oacc[8][4] = {};

    for (int kt = 0; kt < 8; kt++) {
        int cur = kt & 1;
        int kbase = 128 + cur * 128;
        int vbase = 384 + cur * 128;

        // ---- S = Q' @ K^T (Q pre-scaled by 0.125) ----
        float sacc[16][4] = {};
        {
            int rn8 = (lane & 7) + (lane >> 4) * 8;
            int ck8 = ((lane >> 3) & 1) * 8;
            #pragma unroll
            for (int nc = 0; nc < 8; nc++) {
                #pragma unroll
                for (int kc = 0; kc < 4; kc++) {
                    u32 kb[4];
                    ldsm4(kb, sptr(&SM[kbase + nc * 16 + rn8][kc * 16 + ck8]));
                    mma16816(sacc[nc * 2],     qa[kc], kb[0], kb[1]);
                    mma16816(sacc[nc * 2 + 1], qa[kc], kb[2], kb[3]);
                }
            }
        }

        // ---- online softmax ----
        float ml0 = mrow0, ml1 = mrow1;
        #pragma unroll
        for (int nj = 0; nj < 16; nj++) {
            ml0 = fmaxf(ml0, fmaxf(sacc[nj][0], sacc[nj][1]));
            ml1 = fmaxf(ml1, fmaxf(sacc[nj][2], sacc[nj][3]));
        }
        ml0 = fmaxf(ml0, __shfl_xor_sync(0xffffffffu, ml0, 1));
        ml0 = fmaxf(ml0, __shfl_xor_sync(0xffffffffu, ml0, 2));
        ml1 = fmaxf(ml1, __shfl_xor_sync(0xffffffffu, ml1, 1));
        ml1 = fmaxf(ml1, __shfl_xor_sync(0xffffffffu, ml1, 2));
        float al0 = __expf(mrow0 - ml0), al1 = __expf(mrow1 - ml1);
        mrow0 = ml0; mrow1 = ml1;
        lsum0 *= al0; lsum1 *= al1;

        u32 pb[16][2];
        #pragma unroll
        for (int nj = 0; nj < 16; nj++) {
            float p0 = __expf(sacc[nj][0] - ml0), p1 = __expf(sacc[nj][1] - ml0);
            float p2 = __expf(sacc[nj][2] - ml1), p3 = __expf(sacc[nj][3] - ml1);
            lsum0 += p0 + p1; lsum1 += p2 + p3;
            pb[nj][0] = pkbf(p0, p1);
            pb[nj][1] = pkbf(p2, p3);
        }
        #pragma unroll
        for (int nj = 0; nj < 8; nj++) {
            oacc[nj][0] *= al0; oacc[nj][1] *= al0;
            oacc[nj][2] *= al1; oacc[nj][3] *= al1;
        }

        // ---- O += P @ V ----
        {
            int vr8 = (lane & 7) + ((lane >> 3) & 1) * 8;
            int vc8 = (lane >> 4) * 8;
            #pragma unroll
            for (int pc = 0; pc < 8; pc++) {
                u32 pa[4] = {pb[pc * 2][0], pb[pc * 2][1], pb[pc * 2 + 1][0], pb[pc * 2 + 1][1]};
                #pragma unroll
                for (int vc = 0; vc < 4; vc++) {
                    u32 vb[4];
                    ldsm4t(vb, sptr(&SM[vbase + pc * 16 + vr8][vc * 16 + vc8]));
                    mma16816(oacc[vc * 2],     pa, vb[0], vb[1]);
                    mma16816(oacc[vc * 2 + 1], pa, vb[2], vb[3]);
                }
            }
        }

        __syncthreads();
        if (kt < 6) {
            int nb = kt + 2;
            LD_ROW128(128 + cur * 128, Kg + (size_t)(nb * 128) * D_)
            LD_ROW128(384 + cur * 128, Vg + (size_t)(nb * 128) * D_)
            CPCOMMIT();
            CPWAIT1();
            __syncthreads();
        } else if (kt == 6) {
            CPWAIT0();
            __syncthreads();
        }
    }

    // ---- normalize + store ----
    lsum0 += __shfl_xor_sync(0xffffffffu, lsum0, 1);
    lsum0 += __shfl_xor_sync(0xffffffffu, lsum0, 2);
    lsum1 += __shfl_xor_sync(0xffffffffu, lsum1, 1);
    lsum1 += __shfl_xor_sync(0xffffffffu, lsum1, 2);
    float inv0 = 1.0f / lsum0, inv1 = 1.0f / lsum1;
    int r0 = m0 + wid * 16 + (lane >> 2);
    #pragma unroll
    for (int nj = 0; nj < 8; nj++) {
        int col = nj * 8 + (lane & 3) * 2;
        size_t b0 = (size_t)(bb * S_ + r0) * HID + h * D_ + col;
        *(__nv_bfloat162*)&g_xc[b0] = __floats2bfloat162_rn(oacc[nj][0] * inv0, oacc[nj][1] * inv0);
        *(__nv_bfloat162*)&g_xc[b0 + 8 * HID] = __floats2bfloat162_rn(oacc[nj][2] * inv1, oacc[nj][3] * inv1);
    }
}

// ============ x = ctx @ Wo + bo + residual (fp32 out) ============
__global__ void __launch_bounds__(256, 2) out_gemm(
    const float* __restrict__ X, const float* __restrict__ bo) {
    __shared__ bf16 As[2][128][56];
    __shared__ bf16 Bs[2][32][136];
    int tid = threadIdx.x, lane = tid & 31, wid = tid >> 5;
    int wm = (wid >> 2) * 64, wn = (wid & 3) * 32;
    int m0 = blockIdx.y * 128, n0 = blockIdx.x * 128;
    float acc[4][4][4] = {};

    int arow = tid >> 1, acol = (tid & 1) * 16;
    int brow = tid >> 3, bcol = (tid & 7) * 16;
    const bf16* Abase = g_xc + (size_t)(m0 + arow) * HID + acol;

    #define OUT_LOAD(KT, BUF)                                                      \
        {                                                                          \
            const bf16* Ag = Abase + (KT) * 32;                                    \
            CP16(sptr(&As[BUF][arow][acol]), Ag);                                  \
            CP16(sptr(&As[BUF][arow][acol + 8]), Ag + 8);                          \
            const bf16* Bg = g_wo + (size_t)((KT) * 32 + brow) * HID + n0 + bcol;  \
            CP16(sptr(&Bs[BUF][brow][bcol]), Bg);                                  \
            CP16(sptr(&Bs[BUF][brow][bcol + 8]), Bg + 8);                          \
        }

    OUT_LOAD(0, 0) CPCOMMIT();
    for (int kt = 0; kt < 24; kt++) {
        int cur = kt & 1;
        if (kt < 23) { OUT_LOAD(kt + 1, cur ^ 1) CPCOMMIT(); CPWAIT1(); }
        else CPWAIT0();
        __syncthreads();
        #pragma unroll
        for (int kk = 0; kk < 2; kk++) {
            u32 a[4][4], bfr[2][4];
            #pragma unroll
            for (int mi = 0; mi < 4; mi++) {
                int r = wm + mi * 16 + (lane & 7) + ((lane >> 3) & 1) * 8;
                int c = kk * 16 + (lane >> 4) * 8;
                ldsm4(a[mi], sptr(&As[cur][r][c]));
            }
            #pragma unroll
            for (int nj = 0; nj < 2; nj++) {
                int rk = kk * 16 + (lane & 7) + ((lane >> 3) & 1) * 8;
                int cn = wn + nj * 16 + (lane >> 4) * 8;
                ldsm4t(bfr[nj], sptr(&Bs[cur][rk][cn]));
            }
            #pragma unroll
            for (int mi = 0; mi < 4; mi++)
                #pragma unroll
                for (int jn = 0; jn < 4; jn++)
                    mma16816(acc[mi][jn], a[mi], bfr[jn >> 1][(jn & 1) * 2], bfr[jn >> 1][(jn & 1) * 2 + 1]);
        }
        __syncthreads();
    }
    #pragma unroll
    for (int mi = 0; mi < 4; mi++) {
        int r0 = m0 + wm + mi * 16 + (lane >> 2);
        #pragma unroll
        for (int jn = 0; jn < 4; jn++) {
            int col = n0 + wn + jn * 8 + (lane & 3) * 2;
            size_t off0 = (size_t)r0 * HID + col;
            size_t off1 = off0 + 8 * HID;
            float2 x0 = *(const float2*)&X[off0];
            float2 x1 = *(const float2*)&X[off1];
            float b0f = bo[col], b1f = bo[col + 1];
            float2 o0 = { acc[mi][jn][0] + b0f + x0.x, acc[mi][jn][1] + b1f + x0.y };
            float2 o1 = { acc[mi][jn][2] + b0f + x1.x, acc[mi][jn][3] + b1f + x1.y };
            *(float2*)&g_x[off0] = o0;
            *(float2*)&g_x[off1] = o1;
        }
    }
}

// ---------------- LayerNorm (fp32) ----------------
__global__ void ln_kernel(const float* __restrict__ gam, const float* __restrict__ bet,
                          float* __restrict__ out) {
    __shared__ float red[256];
    int row = blockIdx.x;
    int tid = threadIdx.x;
    const float* xr = g_x + (size_t)row * HID;
    float v0 = xr[tid], v1 = xr[tid + 256], v2 = xr[tid + 512];
    red[tid] = v0 + v1 + v2;
    __syncthreads();
    #pragma unroll
    for (int o = 128; o > 0; o >>= 1) {
        if (tid < o) red[tid] += red[tid + o];
        __syncthreads();
    }
    float mu = red[0] * (1.0f / HID);
    __syncthreads();
    float d0 = v0 - mu, d1 = v1 - mu, d2 = v2 - mu;
    red[tid] = d0 * d0 + d1 * d1 + d2 * d2;
    __syncthreads();
    #pragma unroll
    for (int o = 128; o > 0; o >>= 1) {
        if (tid < o) red[tid] += red[tid + o];
        __syncthreads();
    }
    float inv = rsqrtf(red[0] * (1.0f / HID) + 1e-12f);
    float* orow = out + (size_t)row * HID;
    orow[tid]       = d0 * inv * gam[tid]       + bet[tid];
    orow[tid + 256] = d1 * inv * gam[tid + 256] + bet[tid + 256];
    orow[tid + 512] = d2 * inv * gam[tid + 512] + bet[tid + 512];
}

// ---------------- launch ----------------
extern "C" void kernel_launch(void* const* d_in, const int* in_sizes, int n_in,
                              void* d_out, int out_size) {
    const float* X  = (const float*)d_in[0];
    const float* Wq = (const float*)d_in[1];
    const float* bq = (const float*)d_in[2];
    const float* Wk = (const float*)d_in[3];
    const float* bk = (const float*)d_in[4];
    const float* Wv = (const float*)d_in[5];
    const float* bv = (const float*)d_in[6];
    const float* Wr = (const float*)d_in[7];
    const float* br = (const float*)d_in[8];
    const float* Wo = (const float*)d_in[9];
    const float* bo = (const float*)d_in[10];
    const float* lg = (const float*)d_in[11];
    const float* lb = (const float*)d_in[12];
    float* out = (float*)d_out;

    bf16 *dwq, *dwk, *dwv, *dwo;
    cudaGetSymbolAddress((void**)&dwq, g_wq);
    cudaGetSymbolAddress((void**)&dwk, g_wk);
    cudaGetSymbolAddress((void**)&dwv, g_wv);
    cudaGetSymbolAddress((void**)&dwo, g_wo);
    cudaFuncSetAttribute(flash_kernel, cudaFuncAttributeMaxDynamicSharedMemorySize, FLASH_SMEM);

    const int NW = HID * HID;       // 589824
    cvt_kernel<<<NW / 1024, 256>>>(Wq, dwq, NW);
    cvt_kernel<<<NW / 1024, 256>>>(Wk, dwk, NW);
    cvt_kernel<<<NW / 1024, 256>>>(Wv, dwv, NW);
    cvt_kernel<<<NW / 1024, 256>>>(Wo, dwo, NW);

    mean_partial_kernel<<<dim3(B_, 32), 256>>>(X);
    router_kernel<<<B_, 256>>>(Wr, br);

    qkv_gemm<<<dim3(HID / 128, NROWS / 128, 3), 256>>>(bq, bk, bv);
    flash_kernel<<<dim3(S_ / 128, NZ), 256, FLASH_SMEM>>>();
    out_gemm<<<dim3(HID / 128, NROWS / 128), 256>>>(X, bo);
    ln_kernel<<<NROWS, 256>>>(lg, lb, out);
}

// round 7
// speedup vs baseline: 10.8034x; 1.2175x over previous
#include <cuda_runtime.h>
#include <cuda_bf16.h>
#include <math.h>

#define B_   8
#define S_   1024
#define H_   12
#define D_   64
#define HID  768
#define KTOP 6
#define NROWS (B_ * S_)        // 8192
#define NZ    (B_ * H_)        // 96
#define NW   (HID * HID)       // 589824

typedef unsigned int u32;
typedef __nv_bfloat16 bf16;

// ---------------- scratch ----------------
__device__ float g_rpart[B_ * 32 * HID];
__device__ float g_mask[NZ];
__device__ bf16  g_xb[NROWS * HID];                // X in bf16
__device__ bf16  g_w[4][NW];                       // Wq, Wk, Wv, Wo in bf16
__device__ bf16  g_q[NZ * S_ * D_];                // Q pre-scaled by 0.125
__device__ bf16  g_k[NZ * S_ * D_];
__device__ bf16  g_v[NZ * S_ * D_];
__device__ bf16  g_xc[NROWS * HID];                // flat ctx bf16
__device__ float g_x[NROWS * HID];                 // pre-LN activations fp32

// ---------------- asm helpers ----------------
__device__ __forceinline__ u32 sptr(const void* p) {
    return (u32)__cvta_generic_to_shared(p);
}
#define CP16(d, s) asm volatile("cp.async.cg.shared.global [%0],[%1],16;\n" :: "r"(d), "l"(s))
#define CPCOMMIT() asm volatile("cp.async.commit_group;\n")
#define CPWAIT0()  asm volatile("cp.async.wait_group 0;\n")
#define CPWAIT1()  asm volatile("cp.async.wait_group 1;\n")

__device__ __forceinline__ void ldsm4(u32 (&r)[4], u32 a) {
    asm volatile("ldmatrix.sync.aligned.m8n8.x4.shared.b16 {%0,%1,%2,%3},[%4];"
                 : "=r"(r[0]), "=r"(r[1]), "=r"(r[2]), "=r"(r[3]) : "r"(a));
}
__device__ __forceinline__ void ldsm4t(u32 (&r)[4], u32 a) {
    asm volatile("ldmatrix.sync.aligned.m8n8.x4.trans.shared.b16 {%0,%1,%2,%3},[%4];"
                 : "=r"(r[0]), "=r"(r[1]), "=r"(r[2]), "=r"(r[3]) : "r"(a));
}
__device__ __forceinline__ void mma16816(float (&d)[4], const u32 (&a)[4], u32 b0, u32 b1) {
    asm volatile(
        "mma.sync.aligned.m16n8k16.row.col.f32.bf16.bf16.f32 "
        "{%0,%1,%2,%3},{%4,%5,%6,%7},{%8,%9},{%0,%1,%2,%3};"
        : "+f"(d[0]), "+f"(d[1]), "+f"(d[2]), "+f"(d[3])
        : "r"(a[0]), "r"(a[1]), "r"(a[2]), "r"(a[3]), "r"(b0), "r"(b1));
}
__device__ __forceinline__ u32 pkbf(float x, float y) {
    __nv_bfloat162 t = __floats2bfloat162_rn(x, y);
    return *(u32*)&t;
}

// ---------------- fp32 -> bf16 conversion: all 4 weights in one launch ----------------
__global__ void cvt4_kernel(const float* __restrict__ a, const float* __restrict__ b,
                            const float* __restrict__ c, const float* __restrict__ d) {
    int w = blockIdx.y;
    const float* s = (w == 0) ? a : (w == 1) ? b : (w == 2) ? c : d;
    bf16* dst = g_w[w];
    int i = (blockIdx.x * 256 + threadIdx.x) * 4;
    float4 v = *(const float4*)(s + i);
    *(__nv_bfloat162*)(dst + i)     = __floats2bfloat162_rn(v.x, v.y);
    *(__nv_bfloat162*)(dst + i + 2) = __floats2bfloat162_rn(v.z, v.w);
}

// ---------------- router path (fp32, exact) + X bf16 conversion ----------------
__global__ void mean_partial_kernel(const float* __restrict__ X) {
    int b = blockIdx.x, chunk = blockIdx.y, tid = threadIdx.x;
    size_t row0 = (size_t)b * S_ + chunk * 32;
    const float* Xb = X + row0 * HID;
    bf16* Ob = g_xb + row0 * HID;
    #pragma unroll
    for (int j = 0; j < 3; j++) {
        int c = tid + j * 256;
        float s = 0.f;
        #pragma unroll 8
        for (int r = 0; r < 32; r++) {
            float v = Xb[r * HID + c];
            s += v;
            Ob[r * HID + c] = __float2bfloat16(v);
        }
        g_rpart[(b * 32 + chunk) * HID + c] = s;
    }
}

__global__ void router_kernel(const float* __restrict__ Wr, const float* __restrict__ br) {
    __shared__ float rin[HID];
    __shared__ float logits[H_];
    int b = blockIdx.x, tid = threadIdx.x;
    #pragma unroll
    for (int j = 0; j < 3; j++) {
        int c = tid + j * 256;
        float s = 0.f;
        #pragma unroll
        for (int p = 0; p < 32; p++) s += g_rpart[(b * 32 + p) * HID + c];
        rin[c] = s * (1.0f / S_);
    }
    __syncthreads();
    int warp = tid >> 5, lane = tid & 31;
    for (int h = warp; h < H_; h += 8) {
        float s = 0.f;
        for (int c = lane; c < HID; c += 32) s += rin[c] * Wr[c * H_ + h];
        #pragma unroll
        for (int o = 16; o > 0; o >>= 1) s += __shfl_xor_sync(0xffffffffu, s, o);
        if (lane == 0) logits[h] = s + br[h];
    }
    __syncthreads();
    if (tid < H_) {
        float v = logits[tid];
        int rank = 0;
        #pragma unroll
        for (int j = 0; j < H_; j++) {
            float u = logits[j];
            if (u > v || (u == v && j < tid)) rank++;
        }
        g_mask[b * H_ + tid] = (rank < KTOP) ? 1.0f : 0.0f;
    }
}

// ============ QKV per-head: C[128,64] tiles, skip masked heads entirely ============
// grid: (H_, NROWS/128, 3); 8 warps as 4m x 2n; validated pv_gemm fragment layout.
__global__ void __launch_bounds__(256, 2) qkv_gemm(
    const float* __restrict__ bq, const float* __restrict__ bk, const float* __restrict__ bv) {
    int head = blockIdx.x;
    int m0 = blockIdx.y * 128;
    int bb = m0 >> 10;
    if (g_mask[bb * H_ + head] == 0.f) return;      // masked head: outputs never read

    __shared__ bf16 As[2][128][56];
    __shared__ bf16 Bs[2][32][72];
    int z = blockIdx.z;
    const bf16* W = g_w[z];
    const float* bias = (z == 0) ? bq : (z == 1) ? bk : bv;
    bf16* out = (z == 0) ? g_q : (z == 1) ? g_k : g_v;
    float qscale = (z == 0) ? 0.125f : 1.0f;        // fold 1/sqrt(D) into Q
    int n0 = head * D_;

    int tid = threadIdx.x, lane = tid & 31, wid = tid >> 5;
    int wm = (wid >> 1) * 32, wn = (wid & 1) * 32;
    float acc[2][4][4] = {};

    int arow = tid >> 1, acol = (tid & 1) * 16;
    int brow = tid >> 3, bcol = (tid & 7) * 8;
    const bf16* Abase = g_xb + (size_t)(m0 + arow) * HID + acol;

    #define QKV_LOAD(KT, BUF)                                                       \
        {                                                                           \
            const bf16* Ag = Abase + (KT) * 32;                                     \
            CP16(sptr(&As[BUF][arow][acol]), Ag);                                   \
            CP16(sptr(&As[BUF][arow][acol + 8]), Ag + 8);                           \
            const bf16* Bg = W + (size_t)((KT) * 32 + brow) * HID + n0 + bcol;      \
            CP16(sptr(&Bs[BUF][brow][bcol]), Bg);                                   \
        }

    QKV_LOAD(0, 0) CPCOMMIT();
    for (int kt = 0; kt < 24; kt++) {
        int cur = kt & 1;
        if (kt < 23) { QKV_LOAD(kt + 1, cur ^ 1) CPCOMMIT(); CPWAIT1(); }
        else CPWAIT0();
        __syncthreads();
        #pragma unroll
        for (int kk = 0; kk < 2; kk++) {
            u32 a[2][4], bfr[2][4];
            #pragma unroll
            for (int mi = 0; mi < 2; mi++) {
                int r = wm + mi * 16 + (lane & 7) + ((lane >> 3) & 1) * 8;
                int c = kk * 16 + (lane >> 4) * 8;
                ldsm4(a[mi], sptr(&As[cur][r][c]));
            }
            #pragma unroll
            for (int nj = 0; nj < 2; nj++) {
                int rk = kk * 16 + (lane & 7) + ((lane >> 3) & 1) * 8;
                int cn = wn + nj * 16 + (lane >> 4) * 8;
                ldsm4t(bfr[nj], sptr(&Bs[cur][rk][cn]));
            }
            #pragma unroll
            for (int mi = 0; mi < 2; mi++)
                #pragma unroll
                for (int jn = 0; jn < 4; jn++)
                    mma16816(acc[mi][jn], a[mi], bfr[jn >> 1][(jn & 1) * 2], bfr[jn >> 1][(jn & 1) * 2 + 1]);
        }
        __syncthreads();
    }

    #pragma unroll
    for (int mi = 0; mi < 2; mi++) {
        int r0 = m0 + wm + mi * 16 + (lane >> 2);
        int s0 = r0 & (S_ - 1);
        #pragma unroll
        for (int jn = 0; jn < 4; jn++) {
            int co = wn + jn * 8 + (lane & 3) * 2;
            float b0f = bias[n0 + co], b1f = bias[n0 + co + 1];
            float c0 = (acc[mi][jn][0] + b0f) * qscale, c1 = (acc[mi][jn][1] + b1f) * qscale;
            float c2 = (acc[mi][jn][2] + b0f) * qscale, c3 = (acc[mi][jn][3] + b1f) * qscale;
            size_t base = ((size_t)(bb * H_ + head) * S_ + s0) * D_ + co;
            *(__nv_bfloat162*)&out[base] = __floats2bfloat162_rn(c0, c1);
            *(__nv_bfloat162*)&out[base + 8 * D_] = __floats2bfloat162_rn(c2, c3);
        }
    }
}

// ============ Flash attention: scores+softmax+PV fused, per (b,h) ============
// smem layout (rows of [72] bf16): Q rows 0-127, K bufs at 128+buf*128, V at 384+buf*128
#define FLASH_SMEM (640 * 72 * 2)

__global__ void __launch_bounds__(256, 1) flash_kernel() {
    extern __shared__ bf16 fsm[];
    bf16 (*SM)[72] = (bf16(*)[72])fsm;
    int z = blockIdx.y;
    int m0 = blockIdx.x * 128;
    int bb = z / H_, h = z % H_;
    int tid = threadIdx.x, lane = tid & 31, wid = tid >> 5;

    if (g_mask[z] == 0.f) {
        // zero-fill ctx tile (128 x 64) so out_gemm sees zeros
        #pragma unroll
        for (int i = tid; i < 2048; i += 256) {
            int row = i >> 4, c4 = (i & 15) << 2;
            *(uint2*)&g_xc[(size_t)(bb * S_ + m0 + row) * HID + h * D_ + c4] = make_uint2(0u, 0u);
        }
        return;
    }

    const bf16* Qg = g_q + ((size_t)z << 16);
    const bf16* Kg = g_k + ((size_t)z << 16);
    const bf16* Vg = g_v + ((size_t)z << 16);

    int arow = tid >> 1, acol = (tid & 1) << 5;    // 2 threads/row, 32 cols each

    #define LD_ROW128(DST, GP)                                        \
        {                                                             \
            u32 d = sptr(&SM[(DST) + arow][acol]);                    \
            const bf16* s = (GP) + (size_t)arow * D_ + acol;          \
            CP16(d, s); CP16(d + 16, s + 8);                          \
            CP16(d + 32, s + 16); CP16(d + 48, s + 24);               \
        }

    LD_ROW128(0, Qg + (size_t)m0 * D_)
    LD_ROW128(128, Kg)
    LD_ROW128(384, Vg)
    CPCOMMIT();
    LD_ROW128(256, Kg + (size_t)128 * D_)
    LD_ROW128(512, Vg + (size_t)128 * D_)
    CPCOMMIT();
    CPWAIT1();
    __syncthreads();

    // Q fragments (register-resident, loaded once)
    u32 qa[4][4];
    {
        int qr = wid * 16 + (lane & 7) + ((lane >> 3) & 1) * 8;
        int qc = (lane >> 4) * 8;
        #pragma unroll
        for (int kc = 0; kc < 4; kc++)
            ldsm4(qa[kc], sptr(&SM[qr][kc * 16 + qc]));
    }

    float mrow0 = -1e30f, mrow1 = -1e30f;
    float lsum0 = 0.f, lsum1 = 0.f;
    float oacc[8][4] = {};

    for (int kt = 0; kt < 8; kt++) {
        int cur = kt & 1;
        int kbase = 128 + cur * 128;
        int vbase = 384 + cur * 128;

        // ---- S = Q' @ K^T (Q pre-scaled by 0.125) ----
        float sacc[16][4] = {};
        {
            int rn8 = (lane & 7) + (lane >> 4) * 8;
            int ck8 = ((lane >> 3) & 1) * 8;
            #pragma unroll
            for (int nc = 0; nc < 8; nc++) {
                #pragma unroll
                for (int kc = 0; kc < 4; kc++) {
                    u32 kb[4];
                    ldsm4(kb, sptr(&SM[kbase + nc * 16 + rn8][kc * 16 + ck8]));
                    mma16816(sacc[nc * 2],     qa[kc], kb[0], kb[1]);
                    mma16816(sacc[nc * 2 + 1], qa[kc], kb[2], kb[3]);
                }
            }
        }

        // ---- online softmax ----
        float ml0 = mrow0, ml1 = mrow1;
        #pragma unroll
        for (int nj = 0; nj < 16; nj++) {
            ml0 = fmaxf(ml0, fmaxf(sacc[nj][0], sacc[nj][1]));
            ml1 = fmaxf(ml1, fmaxf(sacc[nj][2], sacc[nj][3]));
        }
        ml0 = fmaxf(ml0, __shfl_xor_sync(0xffffffffu, ml0, 1));
        ml0 = fmaxf(ml0, __shfl_xor_sync(0xffffffffu, ml0, 2));
        ml1 = fmaxf(ml1, __shfl_xor_sync(0xffffffffu, ml1, 1));
        ml1 = fmaxf(ml1, __shfl_xor_sync(0xffffffffu, ml1, 2));
        float al0 = __expf(mrow0 - ml0), al1 = __expf(mrow1 - ml1);
        mrow0 = ml0; mrow1 = ml1;
        lsum0 *= al0; lsum1 *= al1;

        u32 pb[16][2];
        #pragma unroll
        for (int nj = 0; nj < 16; nj++) {
            float p0 = __expf(sacc[nj][0] - ml0), p1 = __expf(sacc[nj][1] - ml0);
            float p2 = __expf(sacc[nj][2] - ml1), p3 = __expf(sacc[nj][3] - ml1);
            lsum0 += p0 + p1; lsum1 += p2 + p3;
            pb[nj][0] = pkbf(p0, p1);
            pb[nj][1] = pkbf(p2, p3);
        }
        #pragma unroll
        for (int nj = 0; nj < 8; nj++) {
            oacc[nj][0] *= al0; oacc[nj][1] *= al0;
            oacc[nj][2] *= al1; oacc[nj][3] *= al1;
        }

        // ---- O += P @ V ----
        {
            int vr8 = (lane & 7) + ((lane >> 3) & 1) * 8;
            int vc8 = (lane >> 4) * 8;
            #pragma unroll
            for (int pc = 0; pc < 8; pc++) {
                u32 pa[4] = {pb[pc * 2][0], pb[pc * 2][1], pb[pc * 2 + 1][0], pb[pc * 2 + 1][1]};
                #pragma unroll
                for (int vc = 0; vc < 4; vc++) {
                    u32 vb[4];
                    ldsm4t(vb, sptr(&SM[vbase + pc * 16 + vr8][vc * 16 + vc8]));
                    mma16816(oacc[vc * 2],     pa, vb[0], vb[1]);
                    mma16816(oacc[vc * 2 + 1], pa, vb[2], vb[3]);
                }
            }
        }

        __syncthreads();
        if (kt < 6) {
            int nb = kt + 2;
            LD_ROW128(128 + cur * 128, Kg + (size_t)(nb * 128) * D_)
            LD_ROW128(384 + cur * 128, Vg + (size_t)(nb * 128) * D_)
            CPCOMMIT();
            CPWAIT1();
            __syncthreads();
        } else if (kt == 6) {
            CPWAIT0();
            __syncthreads();
        }
    }

    // ---- normalize + store ----
    lsum0 += __shfl_xor_sync(0xffffffffu, lsum0, 1);
    lsum0 += __shfl_xor_sync(0xffffffffu, lsum0, 2);
    lsum1 += __shfl_xor_sync(0xffffffffu, lsum1, 1);
    lsum1 += __shfl_xor_sync(0xffffffffu, lsum1, 2);
    float inv0 = 1.0f / lsum0, inv1 = 1.0f / lsum1;
    int r0 = m0 + wid * 16 + (lane >> 2);
    #pragma unroll
    for (int nj = 0; nj < 8; nj++) {
        int col = nj * 8 + (lane & 3) * 2;
        size_t b0 = (size_t)(bb * S_ + r0) * HID + h * D_ + col;
        *(__nv_bfloat162*)&g_xc[b0] = __floats2bfloat162_rn(oacc[nj][0] * inv0, oacc[nj][1] * inv0);
        *(__nv_bfloat162*)&g_xc[b0 + 8 * HID] = __floats2bfloat162_rn(oacc[nj][2] * inv1, oacc[nj][3] * inv1);
    }
}

// ============ x = ctx @ Wo + bo + residual (fp32 out) ============
__global__ void __launch_bounds__(256, 2) out_gemm(
    const float* __restrict__ X, const float* __restrict__ bo) {
    __shared__ bf16 As[2][128][56];
    __shared__ bf16 Bs[2][32][136];
    int tid = threadIdx.x, lane = tid & 31, wid = tid >> 5;
    int wm = (wid >> 2) * 64, wn = (wid & 3) * 32;
    int m0 = blockIdx.y * 128, n0 = blockIdx.x * 128;
    float acc[4][4][4] = {};

    int arow = tid >> 1, acol = (tid & 1) * 16;
    int brow = tid >> 3, bcol = (tid & 7) * 16;
    const bf16* Abase = g_xc + (size_t)(m0 + arow) * HID + acol;

    #define OUT_LOAD(KT, BUF)                                                        \
        {                                                                            \
            const bf16* Ag = Abase + (KT) * 32;                                      \
            CP16(sptr(&As[BUF][arow][acol]), Ag);                                    \
            CP16(sptr(&As[BUF][arow][acol + 8]), Ag + 8);                            \
            const bf16* Bg = g_w[3] + (size_t)((KT) * 32 + brow) * HID + n0 + bcol;  \
            CP16(sptr(&Bs[BUF][brow][bcol]), Bg);                                    \
            CP16(sptr(&Bs[BUF][brow][bcol + 8]), Bg + 8);                            \
        }

    OUT_LOAD(0, 0) CPCOMMIT();
    for (int kt = 0; kt < 24; kt++) {
        int cur = kt & 1;
        if (kt < 23) { OUT_LOAD(kt + 1, cur ^ 1) CPCOMMIT(); CPWAIT1(); }
        else CPWAIT0();
        __syncthreads();
        #pragma unroll
        for (int kk = 0; kk < 2; kk++) {
            u32 a[4][4], bfr[2][4];
            #pragma unroll
            for (int mi = 0; mi < 4; mi++) {
                int r = wm + mi * 16 + (lane & 7) + ((lane >> 3) & 1) * 8;
                int c = kk * 16 + (lane >> 4) * 8;
                ldsm4(a[mi], sptr(&As[cur][r][c]));
            }
            #pragma unroll
            for (int nj = 0; nj < 2; nj++) {
                int rk = kk * 16 + (lane & 7) + ((lane >> 3) & 1) * 8;
                int cn = wn + nj * 16 + (lane >> 4) * 8;
                ldsm4t(bfr[nj], sptr(&Bs[cur][rk][cn]));
            }
            #pragma unroll
            for (int mi = 0; mi < 4; mi++)
                #pragma unroll
                for (int jn = 0; jn < 4; jn++)
                    mma16816(acc[mi][jn], a[mi], bfr[jn >> 1][(jn & 1) * 2], bfr[jn >> 1][(jn & 1) * 2 + 1]);
        }
        __syncthreads();
    }
    #pragma unroll
    for (int mi = 0; mi < 4; mi++) {
        int r0 = m0 + wm + mi * 16 + (lane >> 2);
        #pragma unroll
        for (int jn = 0; jn < 4; jn++) {
            int col = n0 + wn + jn * 8 + (lane & 3) * 2;
            size_t off0 = (size_t)r0 * HID + col;
            size_t off1 = off0 + 8 * HID;
            float2 x0 = *(const float2*)&X[off0];
            float2 x1 = *(const float2*)&X[off1];
            float b0f = bo[col], b1f = bo[col + 1];
            float2 o0 = { acc[mi][jn][0] + b0f + x0.x, acc[mi][jn][1] + b1f + x0.y };
            float2 o1 = { acc[mi][jn][2] + b0f + x1.x, acc[mi][jn][3] + b1f + x1.y };
            *(float2*)&g_x[off0] = o0;
            *(float2*)&g_x[off1] = o1;
        }
    }
}

// ---------------- LayerNorm (fp32) ----------------
__global__ void ln_kernel(const float* __restrict__ gam, const float* __restrict__ bet,
                          float* __restrict__ out) {
    __shared__ float red[256];
    int row = blockIdx.x;
    int tid = threadIdx.x;
    const float* xr = g_x + (size_t)row * HID;
    float v0 = xr[tid], v1 = xr[tid + 256], v2 = xr[tid + 512];
    red[tid] = v0 + v1 + v2;
    __syncthreads();
    #pragma unroll
    for (int o = 128; o > 0; o >>= 1) {
        if (tid < o) red[tid] += red[tid + o];
        __syncthreads();
    }
    float mu = red[0] * (1.0f / HID);
    __syncthreads();
    float d0 = v0 - mu, d1 = v1 - mu, d2 = v2 - mu;
    red[tid] = d0 * d0 + d1 * d1 + d2 * d2;
    __syncthreads();
    #pragma unroll
    for (int o = 128; o > 0; o >>= 1) {
        if (tid < o) red[tid] += red[tid + o];
        __syncthreads();
    }
    float inv = rsqrtf(red[0] * (1.0f / HID) + 1e-12f);
    float* orow = out + (size_t)row * HID;
    orow[tid]       = d0 * inv * gam[tid]       + bet[tid];
    orow[tid + 256] = d1 * inv * gam[tid + 256] + bet[tid + 256];
    orow[tid + 512] = d2 * inv * gam[tid + 512] + bet[tid + 512];
}

// ---------------- launch ----------------
extern "C" void kernel_launch(void* const* d_in, const int* in_sizes, int n_in,
                              void* d_out, int out_size) {
    const float* X  = (const float*)d_in[0];
    const float* Wq = (const float*)d_in[1];
    const float* bq = (const float*)d_in[2];
    const float* Wk = (const float*)d_in[3];
    const float* bk = (const float*)d_in[4];
    const float* Wv = (const float*)d_in[5];
    const float* bv = (const float*)d_in[6];
    const float* Wr = (const float*)d_in[7];
    const float* br = (const float*)d_in[8];
    const float* Wo = (const float*)d_in[9];
    const float* bo = (const float*)d_in[10];
    const float* lg = (const float*)d_in[11];
    const float* lb = (const float*)d_in[12];
    float* out = (float*)d_out;

    cudaFuncSetAttribute(flash_kernel, cudaFuncAttributeMaxDynamicSharedMemorySize, FLASH_SMEM);

    cvt4_kernel<<<dim3(NW / 1024, 4), 256>>>(Wq, Wk, Wv, Wo);
    mean_partial_kernel<<<dim3(B_, 32), 256>>>(X);
    router_kernel<<<B_, 256>>>(Wr, br);

    qkv_gemm<<<dim3(H_, NROWS / 128, 3), 256>>>(bq, bk, bv);
    flash_kernel<<<dim3(S_ / 128, NZ), 256, FLASH_SMEM>>>();
    out_gemm<<<dim3(HID / 128, NROWS / 128), 256>>>(X, bo);
    ln_kernel<<<NROWS, 256>>>(lg, lb, out);
}